// round 5
// baseline (speedup 1.0000x reference)
#include <cuda_runtime.h>
#include <cuda_bf16.h>

#define BB 8
#define CC 96
#define C3 288
#define HH 192
#define WW 192
#define HWP (HH*WW)
#define NH 3
#define HD 32
#define NCHUNK 16
#define CHUNK (HWP/NCHUNK)
#define PXT 128
#define NPXT (HWP/PXT)      // 288
#define AST 136             // act smem stride for k1/k5
#define GST 132             // gram smem stride

typedef unsigned long long u64;
typedef unsigned int u32;

// ---------------- scratch ----------------
__device__ __nv_bfloat16 g_qkv [(size_t)BB*C3*HWP];
__device__ __nv_bfloat16 g_qkvd[(size_t)BB*C3*HWP];
__device__ float g_Sp  [NCHUNK*BB*NH*HD*HD];
__device__ float g_sqp [NCHUNK*BB*192];
__device__ float g_A   [BB*NH*HD*HD];
// packed tf32 weights (A-fragment order)
__device__ float g_pk_qkv [288*96];
__device__ float g_pk_proj[96*96];
__device__ float g_pk_c1  [192*96];
__device__ float g_pk_c2  [96*96];

// ---------------- helpers ----------------
__device__ __forceinline__ float tf32r(float v) {
    u32 u; asm("cvt.rna.tf32.f32 %0, %1;" : "=r"(u) : "f"(v));
    return __uint_as_float(u);
}
__device__ __forceinline__ void mma8(float d[4], const u32 a[4], u32 b0, u32 b1) {
    asm volatile(
        "mma.sync.aligned.m16n8k8.row.col.f32.tf32.tf32.f32 "
        "{%0,%1,%2,%3},{%4,%5,%6,%7},{%8,%9},{%0,%1,%2,%3};"
        : "+f"(d[0]), "+f"(d[1]), "+f"(d[2]), "+f"(d[3])
        : "r"(a[0]), "r"(a[1]), "r"(a[2]), "r"(a[3]), "r"(b0), "r"(b1));
}
__device__ __forceinline__ void ldA(u32 a[4], const float* pk, int frag, int lane) {
    float4 f = *(const float4*)(pk + (size_t)frag*128 + lane*4);
    a[0] = __float_as_uint(f.x); a[1] = __float_as_uint(f.y);
    a[2] = __float_as_uint(f.z); a[3] = __float_as_uint(f.w);
}
// load 4 consecutive bf16 -> float4 (8-byte load)
__device__ __forceinline__ float4 ldbf4(const __nv_bfloat16* p) {
    uint2 raw = *(const uint2*)p;
    __nv_bfloat162 p0 = *reinterpret_cast<__nv_bfloat162*>(&raw.x);
    __nv_bfloat162 p1 = *reinterpret_cast<__nv_bfloat162*>(&raw.y);
    float2 f0 = __bfloat1622float2(p0), f1 = __bfloat1622float2(p1);
    return make_float4(f0.x, f0.y, f1.x, f1.y);
}

// ============ K0: pack weights into tf32 A-fragment order ============
__global__ void k0_pack(const float* __restrict__ qkvw, const float* __restrict__ projw,
                        const float* __restrict__ c1w,  const float* __restrict__ c2w)
{
    int e = blockIdx.x*256 + threadIdx.x;
    const float* src; float* dst; int idx = e;
    if      (idx < 27648) { src = qkvw; dst = g_pk_qkv; }
    else if (idx < 36864) { idx -= 27648; src = projw; dst = g_pk_proj; }
    else if (idx < 55296) { idx -= 36864; src = c1w;  dst = g_pk_c1; }
    else if (idx < 64512) { idx -= 55296; src = c2w;  dst = g_pk_c2; }
    else return;
    int f = idx >> 7, L = (idx >> 2) & 31, r = idx & 3;
    int mt = f / 12, ks = f % 12;
    int row = mt*16 + (L >> 2) + (r & 1)*8;
    int col = ks*8 + (L & 3) + ((r >> 1) & 1)*4;
    dst[idx] = tf32r(src[row*96 + col]);
}

// ============ K1: LN1 + qkv (tensor cores, bf16 out) ============
__global__ void __launch_bounds__(256) k1_ln_qkv(
    const float* __restrict__ x,    const float* __restrict__ ln1w,
    const float* __restrict__ ln1b, const float* __restrict__ qkvb)
{
    extern __shared__ __align__(16) float xs[];   // 96 * AST
    int b  = blockIdx.x / NPXT;
    int p0 = (blockIdx.x % NPXT) * PXT;
    int tid = threadIdx.x;

    const float* xb = x + (size_t)b*CC*HWP + p0;
    for (int idx = tid; idx < 96*32; idx += 256) {
        int c = idx >> 5, t4 = (idx & 31) * 4;
        *(float4*)(xs + c*AST + t4) = *(const float4*)(xb + (size_t)c*HWP + t4);
    }
    __syncthreads();
    if (tid < PXT) {
        float s = 0.f, s2 = 0.f;
        #pragma unroll
        for (int c = 0; c < 96; c++) { float v = xs[c*AST + tid]; s += v; s2 += v*v; }
        float mu  = s * (1.0f/96.0f);
        float var = fmaxf(s2 * (1.0f/96.0f) - mu*mu, 0.f);
        float rs  = rsqrtf(var + 1e-6f);
        #pragma unroll
        for (int c = 0; c < 96; c++) {
            float v = xs[c*AST + tid];
            xs[c*AST + tid] = tf32r((v - mu) * rs * ln1w[c] + ln1b[c]);
        }
    }
    __syncthreads();

    int w = tid >> 5, lane = tid & 31;
    int g = lane >> 2, tig = lane & 3;
    int pxw = w * 16;
    #pragma unroll 1
    for (int mtp = 0; mtp < 9; mtp++) {
        float D[2][2][4];
        #pragma unroll
        for (int m = 0; m < 2; m++)
            #pragma unroll
            for (int n = 0; n < 2; n++)
                #pragma unroll
                for (int c = 0; c < 4; c++) D[m][n][c] = 0.f;
        #pragma unroll 2
        for (int ks = 0; ks < 12; ks++) {
            u32 A0[4], A1[4];
            ldA(A0, g_pk_qkv, (2*mtp)*12 + ks, lane);
            ldA(A1, g_pk_qkv, (2*mtp + 1)*12 + ks, lane);
            u32 b00 = __float_as_uint(xs[(ks*8 + tig)*AST + pxw + g]);
            u32 b01 = __float_as_uint(xs[(ks*8 + tig + 4)*AST + pxw + g]);
            u32 b10 = __float_as_uint(xs[(ks*8 + tig)*AST + pxw + 8 + g]);
            u32 b11 = __float_as_uint(xs[(ks*8 + tig + 4)*AST + pxw + 8 + g]);
            mma8(D[0][0], A0, b00, b01); mma8(D[0][1], A0, b10, b11);
            mma8(D[1][0], A1, b00, b01); mma8(D[1][1], A1, b10, b11);
        }
        #pragma unroll
        for (int m = 0; m < 2; m++) {
            int r0 = (2*mtp + m)*16 + g;
            float bz0 = qkvb[r0], bz1 = qkvb[r0 + 8];
            #pragma unroll
            for (int n = 0; n < 2; n++) {
                int c0 = p0 + pxw + n*8 + 2*tig;
                *(__nv_bfloat162*)(g_qkv + ((size_t)b*C3 + r0)*HWP + c0) =
                    __float22bfloat162_rn(make_float2(D[m][n][0] + bz0, D[m][n][1] + bz0));
                *(__nv_bfloat162*)(g_qkv + ((size_t)b*C3 + r0 + 8)*HWP + c0) =
                    __float22bfloat162_rn(make_float2(D[m][n][2] + bz1, D[m][n][3] + bz1));
            }
        }
    }
}

// ============ K2: depthwise 3x3, SAME (bf16 in/out) ============
__global__ void __launch_bounds__(192) k2_dw(const float* __restrict__ dww,
                                             const float* __restrict__ dwb)
{
    __shared__ float rows[10][WW];
    int bc = blockIdx.x;
    int ch = bc % C3;
    int y0 = blockIdx.y * 8;
    int tid = threadIdx.x;
    const __nv_bfloat16* in = g_qkv + (size_t)bc * HWP;
    // 10 rows x 192 px = 960 bf16x2 pairs; 192 threads -> 5 pairs each
    for (int idx = tid; idx < 960; idx += 192) {
        int r = idx / 96, cx = (idx % 96) * 2;
        int y = y0 - 1 + r;
        float2 v = (y >= 0 && y < HH)
            ? __bfloat1622float2(*(const __nv_bfloat162*)(in + y*WW + cx))
            : make_float2(0.f, 0.f);
        rows[r][cx] = v.x; rows[r][cx + 1] = v.y;
    }
    __syncthreads();
    float w[9];
    #pragma unroll
    for (int q = 0; q < 9; q++) w[q] = dww[ch*9 + q];
    float bias = dwb[ch];
    __nv_bfloat16* outp = g_qkvd + (size_t)bc * HWP;
    int xc = tid;
    bool hasL = (xc > 0), hasR = (xc < WW - 1);
    #pragma unroll
    for (int ry = 0; ry < 8; ry++) {
        float acc = bias;
        #pragma unroll
        for (int dy = 0; dy < 3; dy++) {
            const float* rr = rows[ry + dy];
            float m = rr[xc];
            float l = hasL ? rr[xc - 1] : 0.f;
            float r2 = hasR ? rr[xc + 1] : 0.f;
            acc += w[dy*3]*l + w[dy*3+1]*m + w[dy*3+2]*r2;
        }
        outp[(y0 + ry)*WW + xc] = __float2bfloat16(acc);
    }
}

// ============ K3: Gram + sumsq on tensor cores (bf16 in) ============
__global__ void __launch_bounds__(256) k3_gram()
{
    __shared__ __align__(16) float sm[2*32*GST];   // qs | ks ; reused for S reduction
    __shared__ float ssq[8][32];
    float* qs = sm;
    float* ks = sm + 32*GST;
    int bh = blockIdx.x, chunk = blockIdx.y;
    int b = bh / NH, h = bh % NH;
    int tid = threadIdx.x;
    int w = tid >> 5, lane = tid & 31;
    int g = lane >> 2, tig = lane & 3;
    const __nv_bfloat16* qbase = g_qkvd + ((size_t)b*C3 + h*HD)*HWP + chunk*CHUNK;
    const __nv_bfloat16* kbase = g_qkvd + ((size_t)b*C3 + 96 + h*HD)*HWP + chunk*CHUNK;

    float D[2][4][4];
    #pragma unroll
    for (int m = 0; m < 2; m++)
        #pragma unroll
        for (int n = 0; n < 4; n++)
            #pragma unroll
            for (int c = 0; c < 4; c++) D[m][n][c] = 0.f;
    float acc = 0.f;
    const float* sq_src = (w < 4) ? qs : ks;
    int pxq = (w & 3) * 32;

    #pragma unroll 1
    for (int st = 0; st < CHUNK/128; st++) {
        int poff = st * 128;
        // stage 128 px of q and k (bf16 -> f32, exact under tf32)
        #pragma unroll
        for (int it = 0; it < 4; it++) {
            int idx = tid + it*256;                  // 0..1023
            int ci = idx >> 5, p4 = (idx & 31) * 4;
            float4 qv = ldbf4(qbase + (size_t)ci*HWP + poff + p4);
            float4 kv = ldbf4(kbase + (size_t)ci*HWP + poff + p4);
            *(float4*)(qs + ci*GST + p4) = qv;
            *(float4*)(ks + ci*GST + p4) = kv;
        }
        __syncthreads();

        // each warp: 16-px K-slice, full 32x32 tile (2 m-tiles x 4 n-tiles)
        #pragma unroll
        for (int kstep = 0; kstep < 2; kstep++) {
            int kk = w*16 + kstep*8;
            u32 A[2][4];
            #pragma unroll
            for (int m = 0; m < 2; m++) {
                A[m][0] = __float_as_uint(qs[(m*16 + g)*GST + kk + tig]);
                A[m][1] = __float_as_uint(qs[(m*16 + g + 8)*GST + kk + tig]);
                A[m][2] = __float_as_uint(qs[(m*16 + g)*GST + kk + tig + 4]);
                A[m][3] = __float_as_uint(qs[(m*16 + g + 8)*GST + kk + tig + 4]);
            }
            #pragma unroll
            for (int n = 0; n < 4; n++) {
                u32 b0 = __float_as_uint(ks[(n*8 + g)*GST + kk + tig]);
                u32 b1 = __float_as_uint(ks[(n*8 + g)*GST + kk + tig + 4]);
                mma8(D[0][n], A[0], b0, b1);
                mma8(D[1][n], A[1], b0, b1);
            }
        }
        // sumsq: warp w handles 32-px quarter of q (w<4) or k (w>=4), ch = lane
        {
            const float* srow = sq_src + lane*GST + pxq;
            #pragma unroll
            for (int p4 = 0; p4 < 32; p4 += 4) {
                float4 v = *(const float4*)(srow + p4);
                acc += v.x*v.x + v.y*v.y + v.z*v.z + v.w*v.w;
            }
        }
        __syncthreads();
    }

    ssq[w][lane] = acc;
    // S reduction: reuse sm (all mma reads done — we just passed the barrier)
    float* sred = sm;
    #pragma unroll
    for (int m = 0; m < 2; m++)
        #pragma unroll
        for (int n = 0; n < 4; n++) {
            int base = w*1024 + (m*16 + g)*32 + n*8 + 2*tig;
            sred[base]          = D[m][n][0];
            sred[base + 1]      = D[m][n][1];
            sred[base + 256]    = D[m][n][2];   // row +8 -> +8*32
            sred[base + 257]    = D[m][n][3];
        }
    __syncthreads();

    float* Sp = g_Sp + (((size_t)chunk*BB + b)*NH + h)*1024;
    #pragma unroll
    for (int it = 0; it < 4; it++) {
        int e = tid + it*256;
        float s = 0.f;
        #pragma unroll
        for (int w8 = 0; w8 < 8; w8++) s += sred[w8*1024 + e];
        Sp[e] = s;
    }
    float* sqp = g_sqp + ((size_t)chunk*BB + b)*192;
    if (tid < 32)
        sqp[h*HD + tid] = ssq[0][tid] + ssq[1][tid] + ssq[2][tid] + ssq[3][tid];
    else if (tid < 64) {
        int l = tid - 32;
        sqp[96 + h*HD + l] = ssq[4][l] + ssq[5][l] + ssq[6][l] + ssq[7][l];
    }
}

// ============ K4: normalize + relu + softmax (8 warps/block) ============
__global__ void __launch_bounds__(256) k4_attn(const float* __restrict__ temp)
{
    int w = threadIdx.x >> 5, lane = threadIdx.x & 31;
    int bh = blockIdx.x*8 + w;
    int b = bh / NH, h = bh % NH;
    float sq = 0.f, sk = 0.f;
    #pragma unroll
    for (int c = 0; c < NCHUNK; c++) {
        const float* sqp = g_sqp + ((size_t)c*BB + b)*192;
        sq += sqp[h*HD + lane];
        sk += sqp[96 + h*HD + lane];
    }
    float nq = fmaxf(sqrtf(sq), 1e-12f);
    float nkv = fmaxf(sqrtf(sk), 1e-12f);
    float tp = temp[h];
    float v[32];
    float mx = 0.f;
    #pragma unroll
    for (int j = 0; j < 32; j++) {
        float nkj = __shfl_sync(0xffffffffu, nkv, j);
        float s = 0.f;
        #pragma unroll
        for (int c = 0; c < NCHUNK; c++)
            s += g_Sp[(((size_t)c*BB + b)*NH + h)*1024 + lane*32 + j];
        s = s / (nq * nkj) * tp;
        s = fmaxf(s, 0.f);
        v[j] = s;
        mx = fmaxf(mx, s);
    }
    float sum = 0.f;
    #pragma unroll
    for (int j = 0; j < 32; j++) { v[j] = expf(v[j] - mx); sum += v[j]; }
    float inv = 1.f / sum;
    #pragma unroll
    for (int j = 0; j < 32; j++)
        g_A[(size_t)bh*1024 + lane*32 + j] = tf32r(v[j] * inv);
}

// ============ K5: attn@v + proj + residual + LN2 + FFN (tensor cores) ============
__global__ void __launch_bounds__(256) k5_fused(
    const float* __restrict__ x,
    const float* __restrict__ ln2w,  const float* __restrict__ ln2b,
    const float* __restrict__ projb,
    const float* __restrict__ c1b,   const float* __restrict__ c2b,
    const float* __restrict__ betac, const float* __restrict__ gamma,
    float* __restrict__ out)
{
    extern __shared__ __align__(16) float sm[];
    float* bufA = sm;               // 96*AST : v -> y -> gated g
    float* bufB = sm + 96*AST;      // 96*AST : attn_out -> yn
    int b  = blockIdx.x / NPXT;
    int p0 = (blockIdx.x % NPXT) * PXT;
    int tid = threadIdx.x;
    int w = tid >> 5, lane = tid & 31;
    int g = lane >> 2, tig = lane & 3;
    int pxw = w * 16;

    // stage 0: v tile -> bufA (bf16 -> f32, exact under tf32)
    const __nv_bfloat16* vbase = g_qkvd + ((size_t)b*C3 + 192)*HWP + p0;
    for (int idx = tid; idx < 96*32; idx += 256) {
        int c = idx >> 5, t4 = (idx & 31) * 4;
        *(float4*)(bufA + c*AST + t4) = ldbf4(vbase + (size_t)c*HWP + t4);
    }
    __syncthreads();

    // stage 1: attn_out = A @ v -> bufB (tf32)
    #pragma unroll 1
    for (int h = 0; h < NH; h++) {
        const float* Ab = g_A + ((size_t)b*NH + h)*1024;
        float D[2][2][4];
        #pragma unroll
        for (int m = 0; m < 2; m++)
            #pragma unroll
            for (int n = 0; n < 2; n++)
                #pragma unroll
                for (int c = 0; c < 4; c++) D[m][n][c] = 0.f;
        #pragma unroll
        for (int ksi = 0; ksi < 4; ksi++) {
            u32 b00 = __float_as_uint(bufA[(32*h + ksi*8 + tig)*AST + pxw + g]);
            u32 b01 = __float_as_uint(bufA[(32*h + ksi*8 + tig + 4)*AST + pxw + g]);
            u32 b10 = __float_as_uint(bufA[(32*h + ksi*8 + tig)*AST + pxw + 8 + g]);
            u32 b11 = __float_as_uint(bufA[(32*h + ksi*8 + tig + 4)*AST + pxw + 8 + g]);
            #pragma unroll
            for (int m = 0; m < 2; m++) {
                u32 a[4];
                int i0 = m*16 + g, j0 = ksi*8 + tig;
                a[0] = __float_as_uint(Ab[i0*32 + j0]);
                a[1] = __float_as_uint(Ab[(i0 + 8)*32 + j0]);
                a[2] = __float_as_uint(Ab[i0*32 + j0 + 4]);
                a[3] = __float_as_uint(Ab[(i0 + 8)*32 + j0 + 4]);
                mma8(D[m][0], a, b00, b01);
                mma8(D[m][1], a, b10, b11);
            }
        }
        #pragma unroll
        for (int m = 0; m < 2; m++) {
            int r0 = 32*h + m*16 + g;
            #pragma unroll
            for (int n = 0; n < 2; n++) {
                int cl = pxw + n*8 + 2*tig;
                bufB[r0*AST + cl]       = tf32r(D[m][n][0]);
                bufB[r0*AST + cl + 1]   = tf32r(D[m][n][1]);
                bufB[(r0+8)*AST + cl]   = tf32r(D[m][n][2]);
                bufB[(r0+8)*AST + cl+1] = tf32r(D[m][n][3]);
            }
        }
    }
    __syncthreads();

    // stage 2: y = x + (proj(attn_out)+pb)*betac -> bufA (fp32) + yreg
    float yreg[48];
    #pragma unroll 1
    for (int mtp = 0; mtp < 3; mtp++) {
        float D[2][2][4];
        #pragma unroll
        for (int m = 0; m < 2; m++)
            #pragma unroll
            for (int n = 0; n < 2; n++)
                #pragma unroll
                for (int c = 0; c < 4; c++) D[m][n][c] = 0.f;
        #pragma unroll 2
        for (int ksi = 0; ksi < 12; ksi++) {
            u32 A0[4], A1[4];
            ldA(A0, g_pk_proj, (2*mtp)*12 + ksi, lane);
            ldA(A1, g_pk_proj, (2*mtp + 1)*12 + ksi, lane);
            u32 b00 = __float_as_uint(bufB[(ksi*8 + tig)*AST + pxw + g]);
            u32 b01 = __float_as_uint(bufB[(ksi*8 + tig + 4)*AST + pxw + g]);
            u32 b10 = __float_as_uint(bufB[(ksi*8 + tig)*AST + pxw + 8 + g]);
            u32 b11 = __float_as_uint(bufB[(ksi*8 + tig + 4)*AST + pxw + 8 + g]);
            mma8(D[0][0], A0, b00, b01); mma8(D[0][1], A0, b10, b11);
            mma8(D[1][0], A1, b00, b01); mma8(D[1][1], A1, b10, b11);
        }
        #pragma unroll
        for (int m = 0; m < 2; m++) {
            int r0 = (2*mtp + m)*16 + g;
            float pb0 = projb[r0], bc0 = betac[r0];
            float pb1 = projb[r0 + 8], bc1 = betac[r0 + 8];
            #pragma unroll
            for (int n = 0; n < 2; n++) {
                int cl = pxw + n*8 + 2*tig;
                float2 xv0 = *(const float2*)(x + ((size_t)b*CC + r0)*HWP + p0 + cl);
                float2 xv1 = *(const float2*)(x + ((size_t)b*CC + r0 + 8)*HWP + p0 + cl);
                float y0 = xv0.x + (D[m][n][0] + pb0)*bc0;
                float y1 = xv0.y + (D[m][n][1] + pb0)*bc0;
                float y2 = xv1.x + (D[m][n][2] + pb1)*bc1;
                float y3 = xv1.y + (D[m][n][3] + pb1)*bc1;
                int yi = ((mtp*2 + m)*2 + n)*4;
                yreg[yi] = y0; yreg[yi+1] = y1; yreg[yi+2] = y2; yreg[yi+3] = y3;
                bufA[r0*AST + cl] = y0;       bufA[r0*AST + cl + 1] = y1;
                bufA[(r0+8)*AST + cl] = y2;   bufA[(r0+8)*AST + cl + 1] = y3;
            }
        }
    }
    __syncthreads();

    // stage 3: LN2(bufA) -> bufB (tf32)
    if (tid < PXT) {
        float s = 0.f, s2 = 0.f;
        #pragma unroll
        for (int c = 0; c < 96; c++) { float v = bufA[c*AST + tid]; s += v; s2 += v*v; }
        float mu  = s * (1.0f/96.0f);
        float var = fmaxf(s2 * (1.0f/96.0f) - mu*mu, 0.f);
        float rs  = rsqrtf(var + 1e-6f);
        #pragma unroll
        for (int c = 0; c < 96; c++) {
            float v = bufA[c*AST + tid];
            bufB[c*AST + tid] = tf32r((v - mu) * rs * ln2w[c] + ln2b[c]);
        }
    }
    __syncthreads();

    // stage 4: g = (conv1a(yn)+b1)*(conv1b(yn)+b2) -> bufA (tf32)
    #pragma unroll 1
    for (int mtp = 0; mtp < 3; mtp++) {
        float D1[2][2][4], D2[2][2][4];
        #pragma unroll
        for (int m = 0; m < 2; m++)
            #pragma unroll
            for (int n = 0; n < 2; n++)
                #pragma unroll
                for (int c = 0; c < 4; c++) { D1[m][n][c] = 0.f; D2[m][n][c] = 0.f; }
        #pragma unroll 1
        for (int ksi = 0; ksi < 12; ksi++) {
            u32 A0[4], A1[4], A2[4], A3[4];
            ldA(A0, g_pk_c1, (2*mtp)*12 + ksi, lane);
            ldA(A1, g_pk_c1, (2*mtp + 1)*12 + ksi, lane);
            ldA(A2, g_pk_c1, (2*mtp + 6)*12 + ksi, lane);
            ldA(A3, g_pk_c1, (2*mtp + 7)*12 + ksi, lane);
            u32 b00 = __float_as_uint(bufB[(ksi*8 + tig)*AST + pxw + g]);
            u32 b01 = __float_as_uint(bufB[(ksi*8 + tig + 4)*AST + pxw + g]);
            u32 b10 = __float_as_uint(bufB[(ksi*8 + tig)*AST + pxw + 8 + g]);
            u32 b11 = __float_as_uint(bufB[(ksi*8 + tig + 4)*AST + pxw + 8 + g]);
            mma8(D1[0][0], A0, b00, b01); mma8(D1[0][1], A0, b10, b11);
            mma8(D1[1][0], A1, b00, b01); mma8(D1[1][1], A1, b10, b11);
            mma8(D2[0][0], A2, b00, b01); mma8(D2[0][1], A2, b10, b11);
            mma8(D2[1][0], A3, b00, b01); mma8(D2[1][1], A3, b10, b11);
        }
        #pragma unroll
        for (int m = 0; m < 2; m++) {
            int r0 = (2*mtp + m)*16 + g;
            float ba0 = c1b[r0], bb0 = c1b[96 + r0];
            float ba1 = c1b[r0 + 8], bb1 = c1b[96 + r0 + 8];
            #pragma unroll
            for (int n = 0; n < 2; n++) {
                int cl = pxw + n*8 + 2*tig;
                bufA[r0*AST + cl]       = tf32r((D1[m][n][0] + ba0)*(D2[m][n][0] + bb0));
                bufA[r0*AST + cl + 1]   = tf32r((D1[m][n][1] + ba0)*(D2[m][n][1] + bb0));
                bufA[(r0+8)*AST + cl]   = tf32r((D1[m][n][2] + ba1)*(D2[m][n][2] + bb1));
                bufA[(r0+8)*AST + cl+1] = tf32r((D1[m][n][3] + ba1)*(D2[m][n][3] + bb1));
            }
        }
    }
    __syncthreads();

    // stage 5: out = y + (conv2(g)+cb)*gamma
    #pragma unroll 1
    for (int mtp = 0; mtp < 3; mtp++) {
        float D[2][2][4];
        #pragma unroll
        for (int m = 0; m < 2; m++)
            #pragma unroll
            for (int n = 0; n < 2; n++)
                #pragma unroll
                for (int c = 0; c < 4; c++) D[m][n][c] = 0.f;
        #pragma unroll 2
        for (int ksi = 0; ksi < 12; ksi++) {
            u32 A0[4], A1[4];
            ldA(A0, g_pk_c2, (2*mtp)*12 + ksi, lane);
            ldA(A1, g_pk_c2, (2*mtp + 1)*12 + ksi, lane);
            u32 b00 = __float_as_uint(bufA[(ksi*8 + tig)*AST + pxw + g]);
            u32 b01 = __float_as_uint(bufA[(ksi*8 + tig + 4)*AST + pxw + g]);
            u32 b10 = __float_as_uint(bufA[(ksi*8 + tig)*AST + pxw + 8 + g]);
            u32 b11 = __float_as_uint(bufA[(ksi*8 + tig + 4)*AST + pxw + 8 + g]);
            mma8(D[0][0], A0, b00, b01); mma8(D[0][1], A0, b10, b11);
            mma8(D[1][0], A1, b00, b01); mma8(D[1][1], A1, b10, b11);
        }
        #pragma unroll
        for (int m = 0; m < 2; m++) {
            int r0 = (2*mtp + m)*16 + g;
            float cb0 = c2b[r0], gm0 = gamma[r0];
            float cb1 = c2b[r0 + 8], gm1 = gamma[r0 + 8];
            #pragma unroll
            for (int n = 0; n < 2; n++) {
                int cl = pxw + n*8 + 2*tig;
                int yi = ((mtp*2 + m)*2 + n)*4;
                float2 o0, o1;
                o0.x = yreg[yi]   + (D[m][n][0] + cb0)*gm0;
                o0.y = yreg[yi+1] + (D[m][n][1] + cb0)*gm0;
                o1.x = yreg[yi+2] + (D[m][n][2] + cb1)*gm1;
                o1.y = yreg[yi+3] + (D[m][n][3] + cb1)*gm1;
                *(float2*)(out + ((size_t)b*CC + r0)*HWP + p0 + cl) = o0;
                *(float2*)(out + ((size_t)b*CC + r0 + 8)*HWP + p0 + cl) = o1;
            }
        }
    }
}

extern "C" void kernel_launch(void* const* d_in, const int* in_sizes, int n_in,
                              void* d_out, int out_size) {
    (void)in_sizes; (void)n_in; (void)out_size;
    const float* x      = (const float*)d_in[0];
    const float* ln1_w  = (const float*)d_in[1];
    const float* ln1_b  = (const float*)d_in[2];
    const float* ln2_w  = (const float*)d_in[3];
    const float* ln2_b  = (const float*)d_in[4];
    const float* qkv_w  = (const float*)d_in[5];
    const float* qkv_b  = (const float*)d_in[6];
    const float* dw_w   = (const float*)d_in[7];
    const float* dw_b   = (const float*)d_in[8];
    const float* temp   = (const float*)d_in[9];
    const float* proj_w = (const float*)d_in[10];
    const float* proj_b = (const float*)d_in[11];
    const float* c1_w   = (const float*)d_in[12];
    const float* c1_b   = (const float*)d_in[13];
    const float* c2_w   = (const float*)d_in[14];
    const float* c2_b   = (const float*)d_in[15];
    const float* betac  = (const float*)d_in[16];
    const float* gamma  = (const float*)d_in[17];
    float* out = (float*)d_out;

    cudaFuncSetAttribute(k1_ln_qkv, cudaFuncAttributeMaxDynamicSharedMemorySize, 96*AST*4);
    cudaFuncSetAttribute(k5_fused,  cudaFuncAttributeMaxDynamicSharedMemorySize, 2*96*AST*4);

    k0_pack<<<252, 256>>>(qkv_w, proj_w, c1_w, c2_w);
    k1_ln_qkv<<<BB*NPXT, 256, 96*AST*4>>>(x, ln1_w, ln1_b, qkv_b);
    k2_dw<<<dim3(BB*C3, HH/8), 192>>>(dw_w, dw_b);
    k3_gram<<<dim3(BB*NH, NCHUNK), 256>>>();
    k4_attn<<<3, 256>>>(temp);
    k5_fused<<<BB*NPXT, 256, 2*96*AST*4>>>(x, ln2_w, ln2_b, proj_b,
                                           c1_b, c2_b, betac, gamma, out);
}

// round 6
// speedup vs baseline: 1.0083x; 1.0083x over previous
#include <cuda_runtime.h>
#include <cuda_bf16.h>

#define BB 8
#define CC 96
#define C3 288
#define HH 192
#define WW 192
#define HWP (HH*WW)
#define NH 3
#define HD 32
#define NCHUNK 32
#define CHUNK (HWP/NCHUNK)   // 1152 px = 6 rows
#define PXT 128
#define NPXT (HWP/PXT)       // 288
#define AST 136              // act smem stride for k1/k5
#define GST 132              // gram smem stride

typedef unsigned long long u64;
typedef unsigned int u32;

// ---------------- scratch ----------------
__device__ __nv_bfloat16 g_qkv [(size_t)BB*C3*HWP];
__device__ __nv_bfloat16 g_qkvd[(size_t)BB*C3*HWP];
__device__ float g_Sp  [NCHUNK*BB*NH*HD*HD];
__device__ float g_sqp [NCHUNK*BB*192];
__device__ float g_A   [BB*NH*HD*HD];
// packed tf32 weights (A-fragment order)
__device__ float g_pk_qkv [288*96];
__device__ float g_pk_proj[96*96];
__device__ float g_pk_c1  [192*96];
__device__ float g_pk_c2  [96*96];

// ---------------- helpers ----------------
__device__ __forceinline__ float tf32r(float v) {
    u32 u; asm("cvt.rna.tf32.f32 %0, %1;" : "=r"(u) : "f"(v));
    return __uint_as_float(u);
}
__device__ __forceinline__ void mma8(float d[4], const u32 a[4], u32 b0, u32 b1) {
    asm volatile(
        "mma.sync.aligned.m16n8k8.row.col.f32.tf32.tf32.f32 "
        "{%0,%1,%2,%3},{%4,%5,%6,%7},{%8,%9},{%0,%1,%2,%3};"
        : "+f"(d[0]), "+f"(d[1]), "+f"(d[2]), "+f"(d[3])
        : "r"(a[0]), "r"(a[1]), "r"(a[2]), "r"(a[3]), "r"(b0), "r"(b1));
}
__device__ __forceinline__ void ldA(u32 a[4], const float* pk, int frag, int lane) {
    float4 f = *(const float4*)(pk + (size_t)frag*128 + lane*4);
    a[0] = __float_as_uint(f.x); a[1] = __float_as_uint(f.y);
    a[2] = __float_as_uint(f.z); a[3] = __float_as_uint(f.w);
}
__device__ __forceinline__ float4 ldbf4(const __nv_bfloat16* p) {
    uint2 raw = *(const uint2*)p;
    __nv_bfloat162 p0 = *reinterpret_cast<__nv_bfloat162*>(&raw.x);
    __nv_bfloat162 p1 = *reinterpret_cast<__nv_bfloat162*>(&raw.y);
    float2 f0 = __bfloat1622float2(p0), f1 = __bfloat1622float2(p1);
    return make_float4(f0.x, f0.y, f1.x, f1.y);
}

// ============ K0: pack weights into tf32 A-fragment order ============
__global__ void k0_pack(const float* __restrict__ qkvw, const float* __restrict__ projw,
                        const float* __restrict__ c1w,  const float* __restrict__ c2w)
{
    int e = blockIdx.x*256 + threadIdx.x;
    const float* src; float* dst; int idx = e;
    if      (idx < 27648) { src = qkvw; dst = g_pk_qkv; }
    else if (idx < 36864) { idx -= 27648; src = projw; dst = g_pk_proj; }
    else if (idx < 55296) { idx -= 36864; src = c1w;  dst = g_pk_c1; }
    else if (idx < 64512) { idx -= 55296; src = c2w;  dst = g_pk_c2; }
    else return;
    int f = idx >> 7, L = (idx >> 2) & 31, r = idx & 3;
    int mt = f / 12, ks = f % 12;
    int row = mt*16 + (L >> 2) + (r & 1)*8;
    int col = ks*8 + (L & 3) + ((r >> 1) & 1)*4;
    dst[idx] = tf32r(src[row*96 + col]);
}

// ============ K1: LN1 + qkv (tensor cores, bf16 out) ============
__global__ void __launch_bounds__(256) k1_ln_qkv(
    const float* __restrict__ x,    const float* __restrict__ ln1w,
    const float* __restrict__ ln1b, const float* __restrict__ qkvb)
{
    extern __shared__ __align__(16) float xs[];   // 96 * AST
    int b  = blockIdx.x / NPXT;
    int p0 = (blockIdx.x % NPXT) * PXT;
    int tid = threadIdx.x;

    const float* xb = x + (size_t)b*CC*HWP + p0;
    for (int idx = tid; idx < 96*32; idx += 256) {
        int c = idx >> 5, t4 = (idx & 31) * 4;
        *(float4*)(xs + c*AST + t4) = *(const float4*)(xb + (size_t)c*HWP + t4);
    }
    __syncthreads();
    if (tid < PXT) {
        float s = 0.f, s2 = 0.f;
        #pragma unroll
        for (int c = 0; c < 96; c++) { float v = xs[c*AST + tid]; s += v; s2 += v*v; }
        float mu  = s * (1.0f/96.0f);
        float var = fmaxf(s2 * (1.0f/96.0f) - mu*mu, 0.f);
        float rs  = rsqrtf(var + 1e-6f);
        #pragma unroll
        for (int c = 0; c < 96; c++) {
            float v = xs[c*AST + tid];
            xs[c*AST + tid] = tf32r((v - mu) * rs * ln1w[c] + ln1b[c]);
        }
    }
    __syncthreads();

    int w = tid >> 5, lane = tid & 31;
    int g = lane >> 2, tig = lane & 3;
    int pxw = w * 16;
    #pragma unroll 1
    for (int mtp = 0; mtp < 9; mtp++) {
        float D[2][2][4];
        #pragma unroll
        for (int m = 0; m < 2; m++)
            #pragma unroll
            for (int n = 0; n < 2; n++)
                #pragma unroll
                for (int c = 0; c < 4; c++) D[m][n][c] = 0.f;
        #pragma unroll 2
        for (int ks = 0; ks < 12; ks++) {
            u32 A0[4], A1[4];
            ldA(A0, g_pk_qkv, (2*mtp)*12 + ks, lane);
            ldA(A1, g_pk_qkv, (2*mtp + 1)*12 + ks, lane);
            u32 b00 = __float_as_uint(xs[(ks*8 + tig)*AST + pxw + g]);
            u32 b01 = __float_as_uint(xs[(ks*8 + tig + 4)*AST + pxw + g]);
            u32 b10 = __float_as_uint(xs[(ks*8 + tig)*AST + pxw + 8 + g]);
            u32 b11 = __float_as_uint(xs[(ks*8 + tig + 4)*AST + pxw + 8 + g]);
            mma8(D[0][0], A0, b00, b01); mma8(D[0][1], A0, b10, b11);
            mma8(D[1][0], A1, b00, b01); mma8(D[1][1], A1, b10, b11);
        }
        #pragma unroll
        for (int m = 0; m < 2; m++) {
            int r0 = (2*mtp + m)*16 + g;
            float bz0 = qkvb[r0], bz1 = qkvb[r0 + 8];
            #pragma unroll
            for (int n = 0; n < 2; n++) {
                int c0 = p0 + pxw + n*8 + 2*tig;
                *(__nv_bfloat162*)(g_qkv + ((size_t)b*C3 + r0)*HWP + c0) =
                    __float22bfloat162_rn(make_float2(D[m][n][0] + bz0, D[m][n][1] + bz0));
                *(__nv_bfloat162*)(g_qkv + ((size_t)b*C3 + r0 + 8)*HWP + c0) =
                    __float22bfloat162_rn(make_float2(D[m][n][2] + bz1, D[m][n][3] + bz1));
            }
        }
    }
}

// ============ K2: depthwise 3x3, SAME — 32-row strips, rolling window ============
__global__ void __launch_bounds__(192) k2_dw(const float* __restrict__ dww,
                                             const float* __restrict__ dwb)
{
    __shared__ float rows[34][WW];
    int bc = blockIdx.x;            // b*288 + ch
    int ch = bc % C3;
    int y0 = blockIdx.y * 32;
    int tid = threadIdx.x;
    const __nv_bfloat16* in = g_qkv + (size_t)bc * HWP;
    // stage 34 rows (y0-1 .. y0+32), bf16x2 loads
    for (int idx = tid; idx < 34*96; idx += 192) {
        int r = idx / 96, cx = (idx % 96) * 2;
        int y = y0 - 1 + r;
        float2 v = (y >= 0 && y < HH)
            ? __bfloat1622float2(*(const __nv_bfloat162*)(in + y*WW + cx))
            : make_float2(0.f, 0.f);
        rows[r][cx] = v.x; rows[r][cx + 1] = v.y;
    }
    __syncthreads();
    float w[9];
    #pragma unroll
    for (int q = 0; q < 9; q++) w[q] = dww[ch*9 + q];
    float bias = dwb[ch];
    __nv_bfloat16* outp = g_qkvd + (size_t)bc * HWP;
    int xc = tid;
    bool hasL = (xc > 0), hasR = (xc < WW - 1);

    // rolling 3-row register window: 3 LDS per output row
    float lw[3], mw[3], rw[3];
    #pragma unroll
    for (int r = 0; r < 2; r++) {
        lw[r] = hasL ? rows[r][xc - 1] : 0.f;
        mw[r] = rows[r][xc];
        rw[r] = hasR ? rows[r][xc + 1] : 0.f;
    }
    #pragma unroll
    for (int ry = 0; ry < 32; ry++) {
        int s2 = (ry + 2) % 3;
        lw[s2] = hasL ? rows[ry + 2][xc - 1] : 0.f;
        mw[s2] = rows[ry + 2][xc];
        rw[s2] = hasR ? rows[ry + 2][xc + 1] : 0.f;
        int s0 = ry % 3, s1 = (ry + 1) % 3;
        float acc = bias
            + w[0]*lw[s0] + w[1]*mw[s0] + w[2]*rw[s0]
            + w[3]*lw[s1] + w[4]*mw[s1] + w[5]*rw[s1]
            + w[6]*lw[s2] + w[7]*mw[s2] + w[8]*rw[s2];
        outp[(y0 + ry)*WW + xc] = __float2bfloat16(acc);
    }
}

// ============ K3: Gram + sumsq on tensor cores (bf16 in) ============
__global__ void __launch_bounds__(256) k3_gram()
{
    __shared__ __align__(16) float sm[2*32*GST];   // qs | ks ; reused for S reduction
    __shared__ float ssq[8][32];
    float* qs = sm;
    float* ks = sm + 32*GST;
    int bh = blockIdx.x, chunk = blockIdx.y;
    int b = bh / NH, h = bh % NH;
    int tid = threadIdx.x;
    int w = tid >> 5, lane = tid & 31;
    int g = lane >> 2, tig = lane & 3;
    const __nv_bfloat16* qbase = g_qkvd + ((size_t)b*C3 + h*HD)*HWP + chunk*CHUNK;
    const __nv_bfloat16* kbase = g_qkvd + ((size_t)b*C3 + 96 + h*HD)*HWP + chunk*CHUNK;

    float D[2][4][4];
    #pragma unroll
    for (int m = 0; m < 2; m++)
        #pragma unroll
        for (int n = 0; n < 4; n++)
            #pragma unroll
            for (int c = 0; c < 4; c++) D[m][n][c] = 0.f;
    float acc = 0.f;
    const float* sq_src = (w < 4) ? qs : ks;
    int pxq = (w & 3) * 32;

    #pragma unroll 1
    for (int st = 0; st < CHUNK/128; st++) {
        int poff = st * 128;
        #pragma unroll
        for (int it = 0; it < 4; it++) {
            int idx = tid + it*256;
            int ci = idx >> 5, p4 = (idx & 31) * 4;
            float4 qv = ldbf4(qbase + (size_t)ci*HWP + poff + p4);
            float4 kv = ldbf4(kbase + (size_t)ci*HWP + poff + p4);
            *(float4*)(qs + ci*GST + p4) = qv;
            *(float4*)(ks + ci*GST + p4) = kv;
        }
        __syncthreads();

        #pragma unroll
        for (int kstep = 0; kstep < 2; kstep++) {
            int kk = w*16 + kstep*8;
            u32 A[2][4];
            #pragma unroll
            for (int m = 0; m < 2; m++) {
                A[m][0] = __float_as_uint(qs[(m*16 + g)*GST + kk + tig]);
                A[m][1] = __float_as_uint(qs[(m*16 + g + 8)*GST + kk + tig]);
                A[m][2] = __float_as_uint(qs[(m*16 + g)*GST + kk + tig + 4]);
                A[m][3] = __float_as_uint(qs[(m*16 + g + 8)*GST + kk + tig + 4]);
            }
            #pragma unroll
            for (int n = 0; n < 4; n++) {
                u32 b0 = __float_as_uint(ks[(n*8 + g)*GST + kk + tig]);
                u32 b1 = __float_as_uint(ks[(n*8 + g)*GST + kk + tig + 4]);
                mma8(D[0][n], A[0], b0, b1);
                mma8(D[1][n], A[1], b0, b1);
            }
        }
        {
            const float* srow = sq_src + lane*GST + pxq;
            #pragma unroll
            for (int p4 = 0; p4 < 32; p4 += 4) {
                float4 v = *(const float4*)(srow + p4);
                acc += v.x*v.x + v.y*v.y + v.z*v.z + v.w*v.w;
            }
        }
        __syncthreads();
    }

    ssq[w][lane] = acc;
    float* sred = sm;
    #pragma unroll
    for (int m = 0; m < 2; m++)
        #pragma unroll
        for (int n = 0; n < 4; n++) {
            int base = w*1024 + (m*16 + g)*32 + n*8 + 2*tig;
            sred[base]          = D[m][n][0];
            sred[base + 1]      = D[m][n][1];
            sred[base + 256]    = D[m][n][2];
            sred[base + 257]    = D[m][n][3];
        }
    __syncthreads();

    float* Sp = g_Sp + (((size_t)chunk*BB + b)*NH + h)*1024;
    #pragma unroll
    for (int it = 0; it < 4; it++) {
        int e = tid + it*256;
        float s = 0.f;
        #pragma unroll
        for (int w8 = 0; w8 < 8; w8++) s += sred[w8*1024 + e];
        Sp[e] = s;
    }
    float* sqp = g_sqp + ((size_t)chunk*BB + b)*192;
    if (tid < 32)
        sqp[h*HD + tid] = ssq[0][tid] + ssq[1][tid] + ssq[2][tid] + ssq[3][tid];
    else if (tid < 64) {
        int l = tid - 32;
        sqp[96 + h*HD + l] = ssq[4][l] + ssq[5][l] + ssq[6][l] + ssq[7][l];
    }
}

// ============ K4: normalize + relu + softmax (8 warps/block) ============
__global__ void __launch_bounds__(256) k4_attn(const float* __restrict__ temp)
{
    int w = threadIdx.x >> 5, lane = threadIdx.x & 31;
    int bh = blockIdx.x*8 + w;
    int b = bh / NH, h = bh % NH;
    float sq = 0.f, sk = 0.f;
    #pragma unroll
    for (int c = 0; c < NCHUNK; c++) {
        const float* sqp = g_sqp + ((size_t)c*BB + b)*192;
        sq += sqp[h*HD + lane];
        sk += sqp[96 + h*HD + lane];
    }
    float nq = fmaxf(sqrtf(sq), 1e-12f);
    float nkv = fmaxf(sqrtf(sk), 1e-12f);
    float tp = temp[h];
    float v[32];
    float mx = 0.f;
    #pragma unroll
    for (int j = 0; j < 32; j++) {
        float nkj = __shfl_sync(0xffffffffu, nkv, j);
        float s = 0.f;
        #pragma unroll
        for (int c = 0; c < NCHUNK; c++)
            s += g_Sp[(((size_t)c*BB + b)*NH + h)*1024 + lane*32 + j];
        s = s / (nq * nkj) * tp;
        s = fmaxf(s, 0.f);
        v[j] = s;
        mx = fmaxf(mx, s);
    }
    float sum = 0.f;
    #pragma unroll
    for (int j = 0; j < 32; j++) { v[j] = expf(v[j] - mx); sum += v[j]; }
    float inv = 1.f / sum;
    #pragma unroll
    for (int j = 0; j < 32; j++)
        g_A[(size_t)bh*1024 + lane*32 + j] = tf32r(v[j] * inv);
}

// ============ K5: attn@v + proj + residual + LN2 + FFN (tensor cores) ============
__global__ void __launch_bounds__(256) k5_fused(
    const float* __restrict__ x,
    const float* __restrict__ ln2w,  const float* __restrict__ ln2b,
    const float* __restrict__ projb,
    const float* __restrict__ c1b,   const float* __restrict__ c2b,
    const float* __restrict__ betac, const float* __restrict__ gamma,
    float* __restrict__ out)
{
    extern __shared__ __align__(16) float sm[];
    float* bufA = sm;               // 96*AST : v -> y -> gated g
    float* bufB = sm + 96*AST;      // 96*AST : attn_out -> yn
    int b  = blockIdx.x / NPXT;
    int p0 = (blockIdx.x % NPXT) * PXT;
    int tid = threadIdx.x;
    int w = tid >> 5, lane = tid & 31;
    int g = lane >> 2, tig = lane & 3;
    int pxw = w * 16;

    const __nv_bfloat16* vbase = g_qkvd + ((size_t)b*C3 + 192)*HWP + p0;
    for (int idx = tid; idx < 96*32; idx += 256) {
        int c = idx >> 5, t4 = (idx & 31) * 4;
        *(float4*)(bufA + c*AST + t4) = ldbf4(vbase + (size_t)c*HWP + t4);
    }
    __syncthreads();

    // stage 1: attn_out = A @ v -> bufB (tf32)
    #pragma unroll 1
    for (int h = 0; h < NH; h++) {
        const float* Ab = g_A + ((size_t)b*NH + h)*1024;
        float D[2][2][4];
        #pragma unroll
        for (int m = 0; m < 2; m++)
            #pragma unroll
            for (int n = 0; n < 2; n++)
                #pragma unroll
                for (int c = 0; c < 4; c++) D[m][n][c] = 0.f;
        #pragma unroll
        for (int ksi = 0; ksi < 4; ksi++) {
            u32 b00 = __float_as_uint(bufA[(32*h + ksi*8 + tig)*AST + pxw + g]);
            u32 b01 = __float_as_uint(bufA[(32*h + ksi*8 + tig + 4)*AST + pxw + g]);
            u32 b10 = __float_as_uint(bufA[(32*h + ksi*8 + tig)*AST + pxw + 8 + g]);
            u32 b11 = __float_as_uint(bufA[(32*h + ksi*8 + tig + 4)*AST + pxw + 8 + g]);
            #pragma unroll
            for (int m = 0; m < 2; m++) {
                u32 a[4];
                int i0 = m*16 + g, j0 = ksi*8 + tig;
                a[0] = __float_as_uint(Ab[i0*32 + j0]);
                a[1] = __float_as_uint(Ab[(i0 + 8)*32 + j0]);
                a[2] = __float_as_uint(Ab[i0*32 + j0 + 4]);
                a[3] = __float_as_uint(Ab[(i0 + 8)*32 + j0 + 4]);
                mma8(D[m][0], a, b00, b01);
                mma8(D[m][1], a, b10, b11);
            }
        }
        #pragma unroll
        for (int m = 0; m < 2; m++) {
            int r0 = 32*h + m*16 + g;
            #pragma unroll
            for (int n = 0; n < 2; n++) {
                int cl = pxw + n*8 + 2*tig;
                bufB[r0*AST + cl]       = tf32r(D[m][n][0]);
                bufB[r0*AST + cl + 1]   = tf32r(D[m][n][1]);
                bufB[(r0+8)*AST + cl]   = tf32r(D[m][n][2]);
                bufB[(r0+8)*AST + cl+1] = tf32r(D[m][n][3]);
            }
        }
    }
    __syncthreads();

    // stage 2: y = x + (proj(attn_out)+pb)*betac -> bufA (fp32) + yreg
    float yreg[48];
    #pragma unroll 1
    for (int mtp = 0; mtp < 3; mtp++) {
        float D[2][2][4];
        #pragma unroll
        for (int m = 0; m < 2; m++)
            #pragma unroll
            for (int n = 0; n < 2; n++)
                #pragma unroll
                for (int c = 0; c < 4; c++) D[m][n][c] = 0.f;
        #pragma unroll 2
        for (int ksi = 0; ksi < 12; ksi++) {
            u32 A0[4], A1[4];
            ldA(A0, g_pk_proj, (2*mtp)*12 + ksi, lane);
            ldA(A1, g_pk_proj, (2*mtp + 1)*12 + ksi, lane);
            u32 b00 = __float_as_uint(bufB[(ksi*8 + tig)*AST + pxw + g]);
            u32 b01 = __float_as_uint(bufB[(ksi*8 + tig + 4)*AST + pxw + g]);
            u32 b10 = __float_as_uint(bufB[(ksi*8 + tig)*AST + pxw + 8 + g]);
            u32 b11 = __float_as_uint(bufB[(ksi*8 + tig + 4)*AST + pxw + 8 + g]);
            mma8(D[0][0], A0, b00, b01); mma8(D[0][1], A0, b10, b11);
            mma8(D[1][0], A1, b00, b01); mma8(D[1][1], A1, b10, b11);
        }
        #pragma unroll
        for (int m = 0; m < 2; m++) {
            int r0 = (2*mtp + m)*16 + g;
            float pb0 = projb[r0], bc0 = betac[r0];
            float pb1 = projb[r0 + 8], bc1 = betac[r0 + 8];
            #pragma unroll
            for (int n = 0; n < 2; n++) {
                int cl = pxw + n*8 + 2*tig;
                float2 xv0 = *(const float2*)(x + ((size_t)b*CC + r0)*HWP + p0 + cl);
                float2 xv1 = *(const float2*)(x + ((size_t)b*CC + r0 + 8)*HWP + p0 + cl);
                float y0 = xv0.x + (D[m][n][0] + pb0)*bc0;
                float y1 = xv0.y + (D[m][n][1] + pb0)*bc0;
                float y2 = xv1.x + (D[m][n][2] + pb1)*bc1;
                float y3 = xv1.y + (D[m][n][3] + pb1)*bc1;
                int yi = ((mtp*2 + m)*2 + n)*4;
                yreg[yi] = y0; yreg[yi+1] = y1; yreg[yi+2] = y2; yreg[yi+3] = y3;
                bufA[r0*AST + cl] = y0;       bufA[r0*AST + cl + 1] = y1;
                bufA[(r0+8)*AST + cl] = y2;   bufA[(r0+8)*AST + cl + 1] = y3;
            }
        }
    }
    __syncthreads();

    // stage 3: LN2(bufA) -> bufB (tf32)
    if (tid < PXT) {
        float s = 0.f, s2 = 0.f;
        #pragma unroll
        for (int c = 0; c < 96; c++) { float v = bufA[c*AST + tid]; s += v; s2 += v*v; }
        float mu  = s * (1.0f/96.0f);
        float var = fmaxf(s2 * (1.0f/96.0f) - mu*mu, 0.f);
        float rs  = rsqrtf(var + 1e-6f);
        #pragma unroll
        for (int c = 0; c < 96; c++) {
            float v = bufA[c*AST + tid];
            bufB[c*AST + tid] = tf32r((v - mu) * rs * ln2w[c] + ln2b[c]);
        }
    }
    __syncthreads();

    // stage 4: g = (conv1a(yn)+b1)*(conv1b(yn)+b2) -> bufA (tf32)
    #pragma unroll 1
    for (int mtp = 0; mtp < 3; mtp++) {
        float D1[2][2][4], D2[2][2][4];
        #pragma unroll
        for (int m = 0; m < 2; m++)
            #pragma unroll
            for (int n = 0; n < 2; n++)
                #pragma unroll
                for (int c = 0; c < 4; c++) { D1[m][n][c] = 0.f; D2[m][n][c] = 0.f; }
        #pragma unroll 1
        for (int ksi = 0; ksi < 12; ksi++) {
            u32 A0[4], A1[4], A2[4], A3[4];
            ldA(A0, g_pk_c1, (2*mtp)*12 + ksi, lane);
            ldA(A1, g_pk_c1, (2*mtp + 1)*12 + ksi, lane);
            ldA(A2, g_pk_c1, (2*mtp + 6)*12 + ksi, lane);
            ldA(A3, g_pk_c1, (2*mtp + 7)*12 + ksi, lane);
            u32 b00 = __float_as_uint(bufB[(ksi*8 + tig)*AST + pxw + g]);
            u32 b01 = __float_as_uint(bufB[(ksi*8 + tig + 4)*AST + pxw + g]);
            u32 b10 = __float_as_uint(bufB[(ksi*8 + tig)*AST + pxw + 8 + g]);
            u32 b11 = __float_as_uint(bufB[(ksi*8 + tig + 4)*AST + pxw + 8 + g]);
            mma8(D1[0][0], A0, b00, b01); mma8(D1[0][1], A0, b10, b11);
            mma8(D1[1][0], A1, b00, b01); mma8(D1[1][1], A1, b10, b11);
            mma8(D2[0][0], A2, b00, b01); mma8(D2[0][1], A2, b10, b11);
            mma8(D2[1][0], A3, b00, b01); mma8(D2[1][1], A3, b10, b11);
        }
        #pragma unroll
        for (int m = 0; m < 2; m++) {
            int r0 = (2*mtp + m)*16 + g;
            float ba0 = c1b[r0], bb0 = c1b[96 + r0];
            float ba1 = c1b[r0 + 8], bb1 = c1b[96 + r0 + 8];
            #pragma unroll
            for (int n = 0; n < 2; n++) {
                int cl = pxw + n*8 + 2*tig;
                bufA[r0*AST + cl]       = tf32r((D1[m][n][0] + ba0)*(D2[m][n][0] + bb0));
                bufA[r0*AST + cl + 1]   = tf32r((D1[m][n][1] + ba0)*(D2[m][n][1] + bb0));
                bufA[(r0+8)*AST + cl]   = tf32r((D1[m][n][2] + ba1)*(D2[m][n][2] + bb1));
                bufA[(r0+8)*AST + cl+1] = tf32r((D1[m][n][3] + ba1)*(D2[m][n][3] + bb1));
            }
        }
    }
    __syncthreads();

    // stage 5: out = y + (conv2(g)+cb)*gamma
    #pragma unroll 1
    for (int mtp = 0; mtp < 3; mtp++) {
        float D[2][2][4];
        #pragma unroll
        for (int m = 0; m < 2; m++)
            #pragma unroll
            for (int n = 0; n < 2; n++)
                #pragma unroll
                for (int c = 0; c < 4; c++) D[m][n][c] = 0.f;
        #pragma unroll 2
        for (int ksi = 0; ksi < 12; ksi++) {
            u32 A0[4], A1[4];
            ldA(A0, g_pk_c2, (2*mtp)*12 + ksi, lane);
            ldA(A1, g_pk_c2, (2*mtp + 1)*12 + ksi, lane);
            u32 b00 = __float_as_uint(bufA[(ksi*8 + tig)*AST + pxw + g]);
            u32 b01 = __float_as_uint(bufA[(ksi*8 + tig + 4)*AST + pxw + g]);
            u32 b10 = __float_as_uint(bufA[(ksi*8 + tig)*AST + pxw + 8 + g]);
            u32 b11 = __float_as_uint(bufA[(ksi*8 + tig + 4)*AST + pxw + 8 + g]);
            mma8(D[0][0], A0, b00, b01); mma8(D[0][1], A0, b10, b11);
            mma8(D[1][0], A1, b00, b01); mma8(D[1][1], A1, b10, b11);
        }
        #pragma unroll
        for (int m = 0; m < 2; m++) {
            int r0 = (2*mtp + m)*16 + g;
            float cb0 = c2b[r0], gm0 = gamma[r0];
            float cb1 = c2b[r0 + 8], gm1 = gamma[r0 + 8];
            #pragma unroll
            for (int n = 0; n < 2; n++) {
                int cl = pxw + n*8 + 2*tig;
                int yi = ((mtp*2 + m)*2 + n)*4;
                float2 o0, o1;
                o0.x = yreg[yi]   + (D[m][n][0] + cb0)*gm0;
                o0.y = yreg[yi+1] + (D[m][n][1] + cb0)*gm0;
                o1.x = yreg[yi+2] + (D[m][n][2] + cb1)*gm1;
                o1.y = yreg[yi+3] + (D[m][n][3] + cb1)*gm1;
                *(float2*)(out + ((size_t)b*CC + r0)*HWP + p0 + cl) = o0;
                *(float2*)(out + ((size_t)b*CC + r0 + 8)*HWP + p0 + cl) = o1;
            }
        }
    }
}

extern "C" void kernel_launch(void* const* d_in, const int* in_sizes, int n_in,
                              void* d_out, int out_size) {
    (void)in_sizes; (void)n_in; (void)out_size;
    const float* x      = (const float*)d_in[0];
    const float* ln1_w  = (const float*)d_in[1];
    const float* ln1_b  = (const float*)d_in[2];
    const float* ln2_w  = (const float*)d_in[3];
    const float* ln2_b  = (const float*)d_in[4];
    const float* qkv_w  = (const float*)d_in[5];
    const float* qkv_b  = (const float*)d_in[6];
    const float* dw_w   = (const float*)d_in[7];
    const float* dw_b   = (const float*)d_in[8];
    const float* temp   = (const float*)d_in[9];
    const float* proj_w = (const float*)d_in[10];
    const float* proj_b = (const float*)d_in[11];
    const float* c1_w   = (const float*)d_in[12];
    const float* c1_b   = (const float*)d_in[13];
    const float* c2_w   = (const float*)d_in[14];
    const float* c2_b   = (const float*)d_in[15];
    const float* betac  = (const float*)d_in[16];
    const float* gamma  = (const float*)d_in[17];
    float* out = (float*)d_out;

    cudaFuncSetAttribute(k1_ln_qkv, cudaFuncAttributeMaxDynamicSharedMemorySize, 96*AST*4);
    cudaFuncSetAttribute(k5_fused,  cudaFuncAttributeMaxDynamicSharedMemorySize, 2*96*AST*4);

    k0_pack<<<252, 256>>>(qkv_w, proj_w, c1_w, c2_w);
    k1_ln_qkv<<<BB*NPXT, 256, 96*AST*4>>>(x, ln1_w, ln1_b, qkv_b);
    k2_dw<<<dim3(BB*C3, HH/32), 192>>>(dw_w, dw_b);
    k3_gram<<<dim3(BB*NH, NCHUNK), 256>>>();
    k4_attn<<<3, 256>>>(temp);
    k5_fused<<<BB*NPXT, 256, 2*96*AST*4>>>(x, ln2_w, ln2_b, proj_b,
                                           c1_b, c2_b, betac, gamma, out);
}

// round 7
// speedup vs baseline: 1.3633x; 1.3521x over previous
#include <cuda_runtime.h>
#include <cuda_bf16.h>

#define BB 8
#define CC 96
#define C3 288
#define HH 192
#define WW 192
#define HWP (HH*WW)
#define NH 3
#define HD 32
#define NCHUNK 32
#define CHUNK (HWP/NCHUNK)   // 1152
#define PXT 128
#define NPXT (HWP/PXT)       // 288
#define SP 136               // act smem stride in u32 words (ch-pair rows)
#define GST 132              // gram smem stride (f32)

typedef unsigned long long u64;
typedef unsigned int u32;

// ---------------- scratch ----------------
__device__ __nv_bfloat16 g_qkv [(size_t)BB*C3*HWP];
__device__ __nv_bfloat16 g_qkvd[(size_t)BB*C3*HWP];
__device__ float g_Sp  [NCHUNK*BB*NH*HD*HD];
__device__ float g_sqp [NCHUNK*BB*192];
__device__ u32   g_Apk [BB*NH*32*16];     // packed bf16x2 attn rows
// packed bf16 weight fragments (A-operand order, uint4 per lane)
__device__ u32 g_pk_qkv [108*128];   // 18 mtiles x 6 ksteps
__device__ u32 g_pk_proj[36*128];    // 6 x 6
__device__ u32 g_pk_c1  [72*128];    // 12 x 6
__device__ u32 g_pk_c2  [36*128];    // 6 x 6

// ---------------- helpers ----------------
__device__ __forceinline__ void mma16(float d[4], const u32 a[4], u32 b0, u32 b1) {
    asm volatile(
        "mma.sync.aligned.m16n8k16.row.col.f32.bf16.bf16.f32 "
        "{%0,%1,%2,%3},{%4,%5,%6,%7},{%8,%9},{%0,%1,%2,%3};"
        : "+f"(d[0]), "+f"(d[1]), "+f"(d[2]), "+f"(d[3])
        : "r"(a[0]), "r"(a[1]), "r"(a[2]), "r"(a[3]), "r"(b0), "r"(b1));
}
// tf32 mma kept for k3
__device__ __forceinline__ void mma8(float d[4], const u32 a[4], u32 b0, u32 b1) {
    asm volatile(
        "mma.sync.aligned.m16n8k8.row.col.f32.tf32.tf32.f32 "
        "{%0,%1,%2,%3},{%4,%5,%6,%7},{%8,%9},{%0,%1,%2,%3};"
        : "+f"(d[0]), "+f"(d[1]), "+f"(d[2]), "+f"(d[3])
        : "r"(a[0]), "r"(a[1]), "r"(a[2]), "r"(a[3]), "r"(b0), "r"(b1));
}
__device__ __forceinline__ void ldAb(u32 a[4], const u32* pk, int frag, int lane) {
    uint4 f = *(const uint4*)(pk + (size_t)frag*128 + lane*4);
    a[0] = f.x; a[1] = f.y; a[2] = f.z; a[3] = f.w;
}
__device__ __forceinline__ float4 ldbf4(const __nv_bfloat16* p) {
    uint2 raw = *(const uint2*)p;
    __nv_bfloat162 p0 = *reinterpret_cast<__nv_bfloat162*>(&raw.x);
    __nv_bfloat162 p1 = *reinterpret_cast<__nv_bfloat162*>(&raw.y);
    float2 f0 = __bfloat1622float2(p0), f1 = __bfloat1622float2(p1);
    return make_float4(f0.x, f0.y, f1.x, f1.y);
}
__device__ __forceinline__ u32 packbf(float lo, float hi) {
    __nv_bfloat162 t = __float22bfloat162_rn(make_float2(lo, hi));
    return *reinterpret_cast<u32*>(&t);
}
// store one bf16 scalar into a ch-pair u32 buffer: (channel r, pixel p)
__device__ __forceinline__ void stbf(u32* buf, int r, int p, float v) {
    reinterpret_cast<__nv_bfloat16*>(buf)[(r >> 1)*(SP*2) + p*2 + (r & 1)] =
        __float2bfloat16(v);
}

// ============ K0: pack weights into bf16 A-fragment order ============
__global__ void k0_pack(const float* __restrict__ qkvw, const float* __restrict__ projw,
                        const float* __restrict__ c1w,  const float* __restrict__ c2w)
{
    int e = blockIdx.x*256 + threadIdx.x;
    const float* src; u32* dst; int idx = e;
    if      (idx < 13824) { src = qkvw; dst = g_pk_qkv; }
    else if (idx < 18432) { idx -= 13824; src = projw; dst = g_pk_proj; }
    else if (idx < 27648) { idx -= 18432; src = c1w;  dst = g_pk_c1; }
    else if (idx < 32256) { idx -= 27648; src = c2w;  dst = g_pk_c2; }
    else return;
    int f = idx >> 7, rem = idx & 127;
    int lane = rem >> 2, q = rem & 3;
    int mt = f / 6, s = f % 6;
    int g = lane >> 2, tig = lane & 3;
    int r  = mt*16 + g + (q & 1)*8;
    int kb = s*16 + 2*tig + (q >> 1)*8;
    dst[idx] = packbf(src[r*96 + kb], src[r*96 + kb + 1]);
}

// ============ K1: LN1 + qkv (bf16 tensor cores) ============
__global__ void __launch_bounds__(256) k1_ln_qkv(
    const float* __restrict__ x,    const float* __restrict__ ln1w,
    const float* __restrict__ ln1b, const float* __restrict__ qkvb)
{
    extern __shared__ __align__(16) u32 smu[];   // 48 * SP u32 (ch-pair packed)
    int b  = blockIdx.x / NPXT;
    int p0 = (blockIdx.x % NPXT) * PXT;
    int tid = threadIdx.x;

    // stage x as bf16 ch-pairs: [c2][px]
    const float* xb = x + (size_t)b*CC*HWP + p0;
    for (int idx = tid; idx < 48*32; idx += 256) {
        int c2 = idx >> 5, p4 = (idx & 31)*4;
        float4 v0 = *(const float4*)(xb + (size_t)(2*c2)*HWP + p4);
        float4 v1 = *(const float4*)(xb + (size_t)(2*c2 + 1)*HWP + p4);
        smu[c2*SP + p4 + 0] = packbf(v0.x, v1.x);
        smu[c2*SP + p4 + 1] = packbf(v0.y, v1.y);
        smu[c2*SP + p4 + 2] = packbf(v0.z, v1.z);
        smu[c2*SP + p4 + 3] = packbf(v0.w, v1.w);
    }
    __syncthreads();
    // LN1 per pixel (column t), in place
    if (tid < PXT) {
        float s = 0.f, s2 = 0.f;
        #pragma unroll
        for (int c2 = 0; c2 < 48; c2++) {
            u32 wv = smu[c2*SP + tid];
            __nv_bfloat162 h = *reinterpret_cast<__nv_bfloat162*>(&wv);
            float2 f = __bfloat1622float2(h);
            s += f.x + f.y; s2 += f.x*f.x + f.y*f.y;
        }
        float mu  = s * (1.0f/96.0f);
        float var = fmaxf(s2 * (1.0f/96.0f) - mu*mu, 0.f);
        float rs  = rsqrtf(var + 1e-6f);
        #pragma unroll
        for (int c2 = 0; c2 < 48; c2++) {
            u32 wv = smu[c2*SP + tid];
            __nv_bfloat162 h = *reinterpret_cast<__nv_bfloat162*>(&wv);
            float2 f = __bfloat1622float2(h);
            float y0 = (f.x - mu)*rs*ln1w[2*c2]   + ln1b[2*c2];
            float y1 = (f.y - mu)*rs*ln1w[2*c2+1] + ln1b[2*c2+1];
            smu[c2*SP + tid] = packbf(y0, y1);
        }
    }
    __syncthreads();

    int w = tid >> 5, lane = tid & 31;
    int g = lane >> 2, tig = lane & 3;
    int pxw = w * 16;
    #pragma unroll 1
    for (int mtp = 0; mtp < 9; mtp++) {
        float D[2][2][4];
        #pragma unroll
        for (int m = 0; m < 2; m++)
            #pragma unroll
            for (int n = 0; n < 2; n++)
                #pragma unroll
                for (int c = 0; c < 4; c++) D[m][n][c] = 0.f;
        #pragma unroll
        for (int s = 0; s < 6; s++) {
            u32 A0[4], A1[4];
            ldAb(A0, g_pk_qkv, (2*mtp)*6 + s, lane);
            ldAb(A1, g_pk_qkv, (2*mtp + 1)*6 + s, lane);
            u32 b00 = smu[(8*s + tig)*SP + pxw + g];
            u32 b01 = smu[(8*s + tig + 4)*SP + pxw + g];
            u32 b10 = smu[(8*s + tig)*SP + pxw + 8 + g];
            u32 b11 = smu[(8*s + tig + 4)*SP + pxw + 8 + g];
            mma16(D[0][0], A0, b00, b01); mma16(D[0][1], A0, b10, b11);
            mma16(D[1][0], A1, b00, b01); mma16(D[1][1], A1, b10, b11);
        }
        #pragma unroll
        for (int m = 0; m < 2; m++) {
            int r0 = (2*mtp + m)*16 + g;
            float bz0 = qkvb[r0], bz1 = qkvb[r0 + 8];
            #pragma unroll
            for (int n = 0; n < 2; n++) {
                int c0 = p0 + pxw + n*8 + 2*tig;
                *(__nv_bfloat162*)(g_qkv + ((size_t)b*C3 + r0)*HWP + c0) =
                    __float22bfloat162_rn(make_float2(D[m][n][0] + bz0, D[m][n][1] + bz0));
                *(__nv_bfloat162*)(g_qkv + ((size_t)b*C3 + r0 + 8)*HWP + c0) =
                    __float22bfloat162_rn(make_float2(D[m][n][2] + bz1, D[m][n][3] + bz1));
            }
        }
    }
}

// ============ K2: depthwise 3x3, SAME — 32-row strips ============
__global__ void __launch_bounds__(192) k2_dw(const float* __restrict__ dww,
                                             const float* __restrict__ dwb)
{
    __shared__ float rows[34][WW];
    int bc = blockIdx.x;
    int ch = bc % C3;
    int y0 = blockIdx.y * 32;
    int tid = threadIdx.x;
    const __nv_bfloat16* in = g_qkv + (size_t)bc * HWP;
    for (int idx = tid; idx < 34*96; idx += 192) {
        int r = idx / 96, cx = (idx % 96) * 2;
        int y = y0 - 1 + r;
        float2 v = (y >= 0 && y < HH)
            ? __bfloat1622float2(*(const __nv_bfloat162*)(in + y*WW + cx))
            : make_float2(0.f, 0.f);
        rows[r][cx] = v.x; rows[r][cx + 1] = v.y;
    }
    __syncthreads();
    float w[9];
    #pragma unroll
    for (int q = 0; q < 9; q++) w[q] = dww[ch*9 + q];
    float bias = dwb[ch];
    __nv_bfloat16* outp = g_qkvd + (size_t)bc * HWP;
    int xc = tid;
    bool hasL = (xc > 0), hasR = (xc < WW - 1);
    float lw[3], mw[3], rw[3];
    #pragma unroll
    for (int r = 0; r < 2; r++) {
        lw[r] = hasL ? rows[r][xc - 1] : 0.f;
        mw[r] = rows[r][xc];
        rw[r] = hasR ? rows[r][xc + 1] : 0.f;
    }
    #pragma unroll
    for (int ry = 0; ry < 32; ry++) {
        int s2 = (ry + 2) % 3;
        lw[s2] = hasL ? rows[ry + 2][xc - 1] : 0.f;
        mw[s2] = rows[ry + 2][xc];
        rw[s2] = hasR ? rows[ry + 2][xc + 1] : 0.f;
        int s0 = ry % 3, s1 = (ry + 1) % 3;
        float acc = bias
            + w[0]*lw[s0] + w[1]*mw[s0] + w[2]*rw[s0]
            + w[3]*lw[s1] + w[4]*mw[s1] + w[5]*rw[s1]
            + w[6]*lw[s2] + w[7]*mw[s2] + w[8]*rw[s2];
        outp[(y0 + ry)*WW + xc] = __float2bfloat16(acc);
    }
}

// ============ K3: Gram + sumsq on tensor cores (tf32, unchanged) ============
__global__ void __launch_bounds__(256) k3_gram()
{
    __shared__ __align__(16) float sm[2*32*GST];
    __shared__ float ssq[8][32];
    float* qs = sm;
    float* ks = sm + 32*GST;
    int bh = blockIdx.x, chunk = blockIdx.y;
    int b = bh / NH, h = bh % NH;
    int tid = threadIdx.x;
    int w = tid >> 5, lane = tid & 31;
    int g = lane >> 2, tig = lane & 3;
    const __nv_bfloat16* qbase = g_qkvd + ((size_t)b*C3 + h*HD)*HWP + chunk*CHUNK;
    const __nv_bfloat16* kbase = g_qkvd + ((size_t)b*C3 + 96 + h*HD)*HWP + chunk*CHUNK;

    float D[2][4][4];
    #pragma unroll
    for (int m = 0; m < 2; m++)
        #pragma unroll
        for (int n = 0; n < 4; n++)
            #pragma unroll
            for (int c = 0; c < 4; c++) D[m][n][c] = 0.f;
    float acc = 0.f;
    const float* sq_src = (w < 4) ? qs : ks;
    int pxq = (w & 3) * 32;

    #pragma unroll 1
    for (int st = 0; st < CHUNK/128; st++) {
        int poff = st * 128;
        #pragma unroll
        for (int it = 0; it < 4; it++) {
            int idx = tid + it*256;
            int ci = idx >> 5, p4 = (idx & 31) * 4;
            float4 qv = ldbf4(qbase + (size_t)ci*HWP + poff + p4);
            float4 kv = ldbf4(kbase + (size_t)ci*HWP + poff + p4);
            *(float4*)(qs + ci*GST + p4) = qv;
            *(float4*)(ks + ci*GST + p4) = kv;
        }
        __syncthreads();

        #pragma unroll
        for (int kstep = 0; kstep < 2; kstep++) {
            int kk = w*16 + kstep*8;
            u32 A[2][4];
            #pragma unroll
            for (int m = 0; m < 2; m++) {
                A[m][0] = __float_as_uint(qs[(m*16 + g)*GST + kk + tig]);
                A[m][1] = __float_as_uint(qs[(m*16 + g + 8)*GST + kk + tig]);
                A[m][2] = __float_as_uint(qs[(m*16 + g)*GST + kk + tig + 4]);
                A[m][3] = __float_as_uint(qs[(m*16 + g + 8)*GST + kk + tig + 4]);
            }
            #pragma unroll
            for (int n = 0; n < 4; n++) {
                u32 b0 = __float_as_uint(ks[(n*8 + g)*GST + kk + tig]);
                u32 b1 = __float_as_uint(ks[(n*8 + g)*GST + kk + tig + 4]);
                mma8(D[0][n], A[0], b0, b1);
                mma8(D[1][n], A[1], b0, b1);
            }
        }
        {
            const float* srow = sq_src + lane*GST + pxq;
            #pragma unroll
            for (int p4 = 0; p4 < 32; p4 += 4) {
                float4 v = *(const float4*)(srow + p4);
                acc += v.x*v.x + v.y*v.y + v.z*v.z + v.w*v.w;
            }
        }
        __syncthreads();
    }

    ssq[w][lane] = acc;
    float* sred = sm;
    #pragma unroll
    for (int m = 0; m < 2; m++)
        #pragma unroll
        for (int n = 0; n < 4; n++) {
            int base = w*1024 + (m*16 + g)*32 + n*8 + 2*tig;
            sred[base]       = D[m][n][0];
            sred[base + 1]   = D[m][n][1];
            sred[base + 256] = D[m][n][2];
            sred[base + 257] = D[m][n][3];
        }
    __syncthreads();

    float* Sp = g_Sp + (((size_t)chunk*BB + b)*NH + h)*1024;
    #pragma unroll
    for (int it = 0; it < 4; it++) {
        int e = tid + it*256;
        float s = 0.f;
        #pragma unroll
        for (int w8 = 0; w8 < 8; w8++) s += sred[w8*1024 + e];
        Sp[e] = s;
    }
    float* sqp = g_sqp + ((size_t)chunk*BB + b)*192;
    if (tid < 32)
        sqp[h*HD + tid] = ssq[0][tid] + ssq[1][tid] + ssq[2][tid] + ssq[3][tid];
    else if (tid < 64) {
        int l = tid - 32;
        sqp[96 + h*HD + l] = ssq[4][l] + ssq[5][l] + ssq[6][l] + ssq[7][l];
    }
}

// ============ K4: normalize + relu + softmax -> packed bf16 attn ============
__global__ void __launch_bounds__(256) k4_attn(const float* __restrict__ temp)
{
    int w = threadIdx.x >> 5, lane = threadIdx.x & 31;
    int bh = blockIdx.x*8 + w;
    int b = bh / NH, h = bh % NH;
    float sq = 0.f, sk = 0.f;
    #pragma unroll
    for (int c = 0; c < NCHUNK; c++) {
        const float* sqp = g_sqp + ((size_t)c*BB + b)*192;
        sq += sqp[h*HD + lane];
        sk += sqp[96 + h*HD + lane];
    }
    float nq = fmaxf(sqrtf(sq), 1e-12f);
    float nkv = fmaxf(sqrtf(sk), 1e-12f);
    float tp = temp[h];
    float v[32];
    float mx = 0.f;
    #pragma unroll
    for (int j = 0; j < 32; j++) {
        float nkj = __shfl_sync(0xffffffffu, nkv, j);
        float s = 0.f;
        #pragma unroll
        for (int c = 0; c < NCHUNK; c++)
            s += g_Sp[(((size_t)c*BB + b)*NH + h)*1024 + lane*32 + j];
        s = s / (nq * nkj) * tp;
        s = fmaxf(s, 0.f);
        v[j] = s;
        mx = fmaxf(mx, s);
    }
    float sum = 0.f;
    #pragma unroll
    for (int j = 0; j < 32; j++) { v[j] = expf(v[j] - mx); sum += v[j]; }
    float inv = 1.f / sum;
    // packed bf16 pairs: row = lane (cout), word kw = cin pair
    u32* dst = g_Apk + ((size_t)bh*32 + lane)*16;
    #pragma unroll
    for (int kw = 0; kw < 16; kw++)
        dst[kw] = packbf(v[2*kw]*inv, v[2*kw + 1]*inv);
}

// ============ K5: attn@v + proj + residual + LN2 + FFN (bf16 tensor cores) ============
__global__ void __launch_bounds__(256) k5_fused(
    const float* __restrict__ x,
    const float* __restrict__ ln2w,  const float* __restrict__ ln2b,
    const float* __restrict__ projb,
    const float* __restrict__ c1b,   const float* __restrict__ c2b,
    const float* __restrict__ betac, const float* __restrict__ gamma,
    float* __restrict__ out)
{
    extern __shared__ __align__(16) u32 smu[];
    u32* bufP1 = smu;                 // v -> gated g      (48*SP u32)
    u32* bufP2 = smu + 48*SP;         // attn_out -> yn    (48*SP u32)
    float* bufY = (float*)(smu + 96*SP);  // y fp32 (96*SP... uses stride SP)
    int b  = blockIdx.x / NPXT;
    int p0 = (blockIdx.x % NPXT) * PXT;
    int tid = threadIdx.x;
    int w = tid >> 5, lane = tid & 31;
    int g = lane >> 2, tig = lane & 3;
    int pxw = w * 16;

    // stage 0: v tile -> bufP1 ch-pair packed (halfword transpose via byte_perm)
    {
        const __nv_bfloat16* vbase = g_qkvd + ((size_t)b*C3 + 192)*HWP + p0;
        for (int idx = tid; idx < 48*64; idx += 256) {
            int c2 = idx >> 6, j = idx & 63;
            u32 r0 = *((const u32*)(vbase + (size_t)(2*c2)*HWP) + j);
            u32 r1 = *((const u32*)(vbase + (size_t)(2*c2 + 1)*HWP) + j);
            bufP1[c2*SP + 2*j]     = __byte_perm(r0, r1, 0x5410);
            bufP1[c2*SP + 2*j + 1] = __byte_perm(r0, r1, 0x7632);
        }
    }
    __syncthreads();

    // stage 1: attn_out = A @ v -> bufP2 (bf16)
    #pragma unroll 1
    for (int h = 0; h < NH; h++) {
        const u32* apk = g_Apk + ((size_t)(b*NH + h))*32*16;
        float D[2][2][4];
        #pragma unroll
        for (int m = 0; m < 2; m++)
            #pragma unroll
            for (int n = 0; n < 2; n++)
                #pragma unroll
                for (int c = 0; c < 4; c++) D[m][n][c] = 0.f;
        #pragma unroll
        for (int s = 0; s < 2; s++) {
            u32 b00 = bufP1[(16*h + 8*s + tig)*SP + pxw + g];
            u32 b01 = bufP1[(16*h + 8*s + tig + 4)*SP + pxw + g];
            u32 b10 = bufP1[(16*h + 8*s + tig)*SP + pxw + 8 + g];
            u32 b11 = bufP1[(16*h + 8*s + tig + 4)*SP + pxw + 8 + g];
            #pragma unroll
            for (int m = 0; m < 2; m++) {
                u32 a[4];
                int rr = m*16 + g;
                a[0] = apk[rr*16 + s*8 + tig];
                a[1] = apk[(rr + 8)*16 + s*8 + tig];
                a[2] = apk[rr*16 + s*8 + tig + 4];
                a[3] = apk[(rr + 8)*16 + s*8 + tig + 4];
                mma16(D[m][0], a, b00, b01);
                mma16(D[m][1], a, b10, b11);
            }
        }
        #pragma unroll
        for (int m = 0; m < 2; m++) {
            int r0 = 32*h + m*16 + g;
            #pragma unroll
            for (int n = 0; n < 2; n++) {
                int cl = pxw + n*8 + 2*tig;
                stbf(bufP2, r0,     cl,     D[m][n][0]);
                stbf(bufP2, r0,     cl + 1, D[m][n][1]);
                stbf(bufP2, r0 + 8, cl,     D[m][n][2]);
                stbf(bufP2, r0 + 8, cl + 1, D[m][n][3]);
            }
        }
    }
    __syncthreads();

    // stage 2: y = x + (proj(attn_out)+pb)*betac -> bufY (fp32) + yreg
    float yreg[48];
    #pragma unroll 1
    for (int mtp = 0; mtp < 3; mtp++) {
        float D[2][2][4];
        #pragma unroll
        for (int m = 0; m < 2; m++)
            #pragma unroll
            for (int n = 0; n < 2; n++)
                #pragma unroll
                for (int c = 0; c < 4; c++) D[m][n][c] = 0.f;
        #pragma unroll
        for (int s = 0; s < 6; s++) {
            u32 A0[4], A1[4];
            ldAb(A0, g_pk_proj, (2*mtp)*6 + s, lane);
            ldAb(A1, g_pk_proj, (2*mtp + 1)*6 + s, lane);
            u32 b00 = bufP2[(8*s + tig)*SP + pxw + g];
            u32 b01 = bufP2[(8*s + tig + 4)*SP + pxw + g];
            u32 b10 = bufP2[(8*s + tig)*SP + pxw + 8 + g];
            u32 b11 = bufP2[(8*s + tig + 4)*SP + pxw + 8 + g];
            mma16(D[0][0], A0, b00, b01); mma16(D[0][1], A0, b10, b11);
            mma16(D[1][0], A1, b00, b01); mma16(D[1][1], A1, b10, b11);
        }
        #pragma unroll
        for (int m = 0; m < 2; m++) {
            int r0 = (2*mtp + m)*16 + g;
            float pb0 = projb[r0], bc0 = betac[r0];
            float pb1 = projb[r0 + 8], bc1 = betac[r0 + 8];
            #pragma unroll
            for (int n = 0; n < 2; n++) {
                int cl = pxw + n*8 + 2*tig;
                float2 xv0 = *(const float2*)(x + ((size_t)b*CC + r0)*HWP + p0 + cl);
                float2 xv1 = *(const float2*)(x + ((size_t)b*CC + r0 + 8)*HWP + p0 + cl);
                float y0 = xv0.x + (D[m][n][0] + pb0)*bc0;
                float y1 = xv0.y + (D[m][n][1] + pb0)*bc0;
                float y2 = xv1.x + (D[m][n][2] + pb1)*bc1;
                float y3 = xv1.y + (D[m][n][3] + pb1)*bc1;
                int yi = ((mtp*2 + m)*2 + n)*4;
                yreg[yi] = y0; yreg[yi+1] = y1; yreg[yi+2] = y2; yreg[yi+3] = y3;
                bufY[r0*SP + cl] = y0;       bufY[r0*SP + cl + 1] = y1;
                bufY[(r0+8)*SP + cl] = y2;   bufY[(r0+8)*SP + cl + 1] = y3;
            }
        }
    }
    __syncthreads();

    // stage 3: LN2(bufY) -> bufP2 (bf16 ch-pairs)
    if (tid < PXT) {
        float s = 0.f, s2 = 0.f;
        #pragma unroll
        for (int c = 0; c < 96; c++) { float v = bufY[c*SP + tid]; s += v; s2 += v*v; }
        float mu  = s * (1.0f/96.0f);
        float var = fmaxf(s2 * (1.0f/96.0f) - mu*mu, 0.f);
        float rs  = rsqrtf(var + 1e-6f);
        #pragma unroll
        for (int c2 = 0; c2 < 48; c2++) {
            float v0 = bufY[(2*c2)*SP + tid];
            float v1 = bufY[(2*c2 + 1)*SP + tid];
            float y0 = (v0 - mu)*rs*ln2w[2*c2]   + ln2b[2*c2];
            float y1 = (v1 - mu)*rs*ln2w[2*c2+1] + ln2b[2*c2+1];
            bufP2[c2*SP + tid] = packbf(y0, y1);
        }
    }
    __syncthreads();

    // stage 4: g = (conv1a(yn)+b1)*(conv1b(yn)+b2) -> bufP1 (bf16)
    #pragma unroll 1
    for (int mtp = 0; mtp < 3; mtp++) {
        float D1[2][2][4], D2[2][2][4];
        #pragma unroll
        for (int m = 0; m < 2; m++)
            #pragma unroll
            for (int n = 0; n < 2; n++)
                #pragma unroll
                for (int c = 0; c < 4; c++) { D1[m][n][c] = 0.f; D2[m][n][c] = 0.f; }
        #pragma unroll 1
        for (int s = 0; s < 6; s++) {
            u32 A0[4], A1[4], A2[4], A3[4];
            ldAb(A0, g_pk_c1, (2*mtp)*6 + s, lane);
            ldAb(A1, g_pk_c1, (2*mtp + 1)*6 + s, lane);
            ldAb(A2, g_pk_c1, (2*mtp + 6)*6 + s, lane);
            ldAb(A3, g_pk_c1, (2*mtp + 7)*6 + s, lane);
            u32 b00 = bufP2[(8*s + tig)*SP + pxw + g];
            u32 b01 = bufP2[(8*s + tig + 4)*SP + pxw + g];
            u32 b10 = bufP2[(8*s + tig)*SP + pxw + 8 + g];
            u32 b11 = bufP2[(8*s + tig + 4)*SP + pxw + 8 + g];
            mma16(D1[0][0], A0, b00, b01); mma16(D1[0][1], A0, b10, b11);
            mma16(D1[1][0], A1, b00, b01); mma16(D1[1][1], A1, b10, b11);
            mma16(D2[0][0], A2, b00, b01); mma16(D2[0][1], A2, b10, b11);
            mma16(D2[1][0], A3, b00, b01); mma16(D2[1][1], A3, b10, b11);
        }
        #pragma unroll
        for (int m = 0; m < 2; m++) {
            int r0 = (2*mtp + m)*16 + g;
            float ba0 = c1b[r0], bb0 = c1b[96 + r0];
            float ba1 = c1b[r0 + 8], bb1 = c1b[96 + r0 + 8];
            #pragma unroll
            for (int n = 0; n < 2; n++) {
                int cl = pxw + n*8 + 2*tig;
                stbf(bufP1, r0,     cl,     (D1[m][n][0] + ba0)*(D2[m][n][0] + bb0));
                stbf(bufP1, r0,     cl + 1, (D1[m][n][1] + ba0)*(D2[m][n][1] + bb0));
                stbf(bufP1, r0 + 8, cl,     (D1[m][n][2] + ba1)*(D2[m][n][2] + bb1));
                stbf(bufP1, r0 + 8, cl + 1, (D1[m][n][3] + ba1)*(D2[m][n][3] + bb1));
            }
        }
    }
    __syncthreads();

    // stage 5: out = y + (conv2(g)+cb)*gamma
    #pragma unroll 1
    for (int mtp = 0; mtp < 3; mtp++) {
        float D[2][2][4];
        #pragma unroll
        for (int m = 0; m < 2; m++)
            #pragma unroll
            for (int n = 0; n < 2; n++)
                #pragma unroll
                for (int c = 0; c < 4; c++) D[m][n][c] = 0.f;
        #pragma unroll
        for (int s = 0; s < 6; s++) {
            u32 A0[4], A1[4];
            ldAb(A0, g_pk_c2, (2*mtp)*6 + s, lane);
            ldAb(A1, g_pk_c2, (2*mtp + 1)*6 + s, lane);
            u32 b00 = bufP1[(8*s + tig)*SP + pxw + g];
            u32 b01 = bufP1[(8*s + tig + 4)*SP + pxw + g];
            u32 b10 = bufP1[(8*s + tig)*SP + pxw + 8 + g];
            u32 b11 = bufP1[(8*s + tig + 4)*SP + pxw + 8 + g];
            mma16(D[0][0], A0, b00, b01); mma16(D[0][1], A0, b10, b11);
            mma16(D[1][0], A1, b00, b01); mma16(D[1][1], A1, b10, b11);
        }
        #pragma unroll
        for (int m = 0; m < 2; m++) {
            int r0 = (2*mtp + m)*16 + g;
            float cb0 = c2b[r0], gm0 = gamma[r0];
            float cb1 = c2b[r0 + 8], gm1 = gamma[r0 + 8];
            #pragma unroll
            for (int n = 0; n < 2; n++) {
                int cl = pxw + n*8 + 2*tig;
                int yi = ((mtp*2 + m)*2 + n)*4;
                float2 o0, o1;
                o0.x = yreg[yi]   + (D[m][n][0] + cb0)*gm0;
                o0.y = yreg[yi+1] + (D[m][n][1] + cb0)*gm0;
                o1.x = yreg[yi+2] + (D[m][n][2] + cb1)*gm1;
                o1.y = yreg[yi+3] + (D[m][n][3] + cb1)*gm1;
                *(float2*)(out + ((size_t)b*CC + r0)*HWP + p0 + cl) = o0;
                *(float2*)(out + ((size_t)b*CC + r0 + 8)*HWP + p0 + cl) = o1;
            }
        }
    }
}

extern "C" void kernel_launch(void* const* d_in, const int* in_sizes, int n_in,
                              void* d_out, int out_size) {
    (void)in_sizes; (void)n_in; (void)out_size;
    const float* x      = (const float*)d_in[0];
    const float* ln1_w  = (const float*)d_in[1];
    const float* ln1_b  = (const float*)d_in[2];
    const float* ln2_w  = (const float*)d_in[3];
    const float* ln2_b  = (const float*)d_in[4];
    const float* qkv_w  = (const float*)d_in[5];
    const float* qkv_b  = (const float*)d_in[6];
    const float* dw_w   = (const float*)d_in[7];
    const float* dw_b   = (const float*)d_in[8];
    const float* temp   = (const float*)d_in[9];
    const float* proj_w = (const float*)d_in[10];
    const float* proj_b = (const float*)d_in[11];
    const float* c1_w   = (const float*)d_in[12];
    const float* c1_b   = (const float*)d_in[13];
    const float* c2_w   = (const float*)d_in[14];
    const float* c2_b   = (const float*)d_in[15];
    const float* betac  = (const float*)d_in[16];
    const float* gamma  = (const float*)d_in[17];
    float* out = (float*)d_out;

    int smem1 = 48*SP*4;                 // 26112 B
    int smem5 = 96*SP*4 + 96*SP*4;       // two u32 bufs + f32 buf = 104448 B
    cudaFuncSetAttribute(k1_ln_qkv, cudaFuncAttributeMaxDynamicSharedMemorySize, smem1);
    cudaFuncSetAttribute(k5_fused,  cudaFuncAttributeMaxDynamicSharedMemorySize, smem5);

    k0_pack<<<126, 256>>>(qkv_w, proj_w, c1_w, c2_w);
    k1_ln_qkv<<<BB*NPXT, 256, smem1>>>(x, ln1_w, ln1_b, qkv_b);
    k2_dw<<<dim3(BB*C3, HH/32), 192>>>(dw_w, dw_b);
    k3_gram<<<dim3(BB*NH, NCHUNK), 256>>>();
    k4_attn<<<3, 256>>>(temp);
    k5_fused<<<BB*NPXT, 256, smem5>>>(x, ln2_w, ln2_b, proj_b,
                                      c1_b, c2_b, betac, gamma, out);
}

// round 8
// speedup vs baseline: 1.3918x; 1.0210x over previous
#include <cuda_runtime.h>
#include <cuda_bf16.h>

#define BB 8
#define CC 96
#define C3 288
#define HH 192
#define WW 192
#define HWP (HH*WW)
#define NH 3
#define HD 32
#define NCHUNK 32
#define CHUNK (HWP/NCHUNK)   // 1152
#define PXT 128
#define NPXT (HWP/PXT)       // 288
#define SP 136               // act smem stride in u32 words (ch-pair rows)

typedef unsigned long long u64;
typedef unsigned int u32;

// ---------------- scratch ----------------
__device__ __nv_bfloat16 g_qkv [(size_t)BB*C3*HWP];
__device__ __nv_bfloat16 g_qkvd[(size_t)BB*C3*HWP];
__device__ float g_Sp  [NCHUNK*BB*NH*HD*HD];
__device__ float g_sqp [NCHUNK*BB*192];
__device__ float g_A   [BB*NH*HD*HD];      // fp32 attention
__device__ u32   g_Wp  [BB*36*128];        // per-batch proj@A, bf16 A-frags
// packed bf16 weight fragments (A-operand order, uint4 per lane)
__device__ u32 g_pk_qkv [108*128];
__device__ u32 g_pk_proj[36*128];
__device__ u32 g_pk_c1  [72*128];
__device__ u32 g_pk_c2  [36*128];

// ---------------- helpers ----------------
__device__ __forceinline__ void mma16(float d[4], const u32 a[4], u32 b0, u32 b1) {
    asm volatile(
        "mma.sync.aligned.m16n8k16.row.col.f32.bf16.bf16.f32 "
        "{%0,%1,%2,%3},{%4,%5,%6,%7},{%8,%9},{%0,%1,%2,%3};"
        : "+f"(d[0]), "+f"(d[1]), "+f"(d[2]), "+f"(d[3])
        : "r"(a[0]), "r"(a[1]), "r"(a[2]), "r"(a[3]), "r"(b0), "r"(b1));
}
__device__ __forceinline__ void ldAb(u32 a[4], const u32* pk, int frag, int lane) {
    uint4 f = *(const uint4*)(pk + (size_t)frag*128 + lane*4);
    a[0] = f.x; a[1] = f.y; a[2] = f.z; a[3] = f.w;
}
__device__ __forceinline__ u32 packbf(float lo, float hi) {
    __nv_bfloat162 t = __float22bfloat162_rn(make_float2(lo, hi));
    return *reinterpret_cast<u32*>(&t);
}
__device__ __forceinline__ void stbf(u32* buf, int r, int p, float v) {
    reinterpret_cast<__nv_bfloat16*>(buf)[(r >> 1)*(SP*2) + p*2 + (r & 1)] =
        __float2bfloat16(v);
}
__device__ __forceinline__ float2 unbf(u32 wv) {
    __nv_bfloat162 h = *reinterpret_cast<__nv_bfloat162*>(&wv);
    return __bfloat1622float2(h);
}

// ============ K0: pack weights into bf16 A-fragment order ============
__global__ void k0_pack(const float* __restrict__ qkvw, const float* __restrict__ projw,
                        const float* __restrict__ c1w,  const float* __restrict__ c2w)
{
    int e = blockIdx.x*256 + threadIdx.x;
    const float* src; u32* dst; int idx = e;
    if      (idx < 13824) { src = qkvw; dst = g_pk_qkv; }
    else if (idx < 18432) { idx -= 13824; src = projw; dst = g_pk_proj; }
    else if (idx < 27648) { idx -= 18432; src = c1w;  dst = g_pk_c1; }
    else if (idx < 32256) { idx -= 27648; src = c2w;  dst = g_pk_c2; }
    else return;
    int f = idx >> 7, rem = idx & 127;
    int lane = rem >> 2, q = rem & 3;
    int mt = f / 6, s = f % 6;
    int g = lane >> 2, tig = lane & 3;
    int r  = mt*16 + g + (q & 1)*8;
    int kb = s*16 + 2*tig + (q >> 1)*8;
    dst[idx] = packbf(src[r*96 + kb], src[r*96 + kb + 1]);
}

// ============ K1: LN1 + qkv (bf16 tensor cores) ============
__global__ void __launch_bounds__(256) k1_ln_qkv(
    const float* __restrict__ x,    const float* __restrict__ ln1w,
    const float* __restrict__ ln1b, const float* __restrict__ qkvb)
{
    extern __shared__ __align__(16) u32 smu[];   // 48 * SP u32
    int b  = blockIdx.x / NPXT;
    int p0 = (blockIdx.x % NPXT) * PXT;
    int tid = threadIdx.x;

    const float* xb = x + (size_t)b*CC*HWP + p0;
    for (int idx = tid; idx < 48*32; idx += 256) {
        int c2 = idx >> 5, p4 = (idx & 31)*4;
        float4 v0 = *(const float4*)(xb + (size_t)(2*c2)*HWP + p4);
        float4 v1 = *(const float4*)(xb + (size_t)(2*c2 + 1)*HWP + p4);
        smu[c2*SP + p4 + 0] = packbf(v0.x, v1.x);
        smu[c2*SP + p4 + 1] = packbf(v0.y, v1.y);
        smu[c2*SP + p4 + 2] = packbf(v0.z, v1.z);
        smu[c2*SP + p4 + 3] = packbf(v0.w, v1.w);
    }
    __syncthreads();
    if (tid < PXT) {
        float s = 0.f, s2 = 0.f;
        #pragma unroll
        for (int c2 = 0; c2 < 48; c2++) {
            float2 f = unbf(smu[c2*SP + tid]);
            s += f.x + f.y; s2 += f.x*f.x + f.y*f.y;
        }
        float mu  = s * (1.0f/96.0f);
        float var = fmaxf(s2 * (1.0f/96.0f) - mu*mu, 0.f);
        float rs  = rsqrtf(var + 1e-6f);
        #pragma unroll
        for (int c2 = 0; c2 < 48; c2++) {
            float2 f = unbf(smu[c2*SP + tid]);
            float y0 = (f.x - mu)*rs*ln1w[2*c2]   + ln1b[2*c2];
            float y1 = (f.y - mu)*rs*ln1w[2*c2+1] + ln1b[2*c2+1];
            smu[c2*SP + tid] = packbf(y0, y1);
        }
    }
    __syncthreads();

    int w = tid >> 5, lane = tid & 31;
    int g = lane >> 2, tig = lane & 3;
    int pxw = w * 16;
    #pragma unroll 1
    for (int mtp = 0; mtp < 9; mtp++) {
        float D[2][2][4];
        #pragma unroll
        for (int m = 0; m < 2; m++)
            #pragma unroll
            for (int n = 0; n < 2; n++)
                #pragma unroll
                for (int c = 0; c < 4; c++) D[m][n][c] = 0.f;
        #pragma unroll
        for (int s = 0; s < 6; s++) {
            u32 A0[4], A1[4];
            ldAb(A0, g_pk_qkv, (2*mtp)*6 + s, lane);
            ldAb(A1, g_pk_qkv, (2*mtp + 1)*6 + s, lane);
            u32 b00 = smu[(8*s + tig)*SP + pxw + g];
            u32 b01 = smu[(8*s + tig + 4)*SP + pxw + g];
            u32 b10 = smu[(8*s + tig)*SP + pxw + 8 + g];
            u32 b11 = smu[(8*s + tig + 4)*SP + pxw + 8 + g];
            mma16(D[0][0], A0, b00, b01); mma16(D[0][1], A0, b10, b11);
            mma16(D[1][0], A1, b00, b01); mma16(D[1][1], A1, b10, b11);
        }
        #pragma unroll
        for (int m = 0; m < 2; m++) {
            int r0 = (2*mtp + m)*16 + g;
            float bz0 = qkvb[r0], bz1 = qkvb[r0 + 8];
            #pragma unroll
            for (int n = 0; n < 2; n++) {
                int c0 = p0 + pxw + n*8 + 2*tig;
                *(__nv_bfloat162*)(g_qkv + ((size_t)b*C3 + r0)*HWP + c0) =
                    __float22bfloat162_rn(make_float2(D[m][n][0] + bz0, D[m][n][1] + bz0));
                *(__nv_bfloat162*)(g_qkv + ((size_t)b*C3 + r0 + 8)*HWP + c0) =
                    __float22bfloat162_rn(make_float2(D[m][n][2] + bz1, D[m][n][3] + bz1));
            }
        }
    }
}

// ============ K2: depthwise 3x3, SAME — 32-row strips ============
__global__ void __launch_bounds__(192) k2_dw(const float* __restrict__ dww,
                                             const float* __restrict__ dwb)
{
    __shared__ float rows[34][WW];
    int bc = blockIdx.x;
    int ch = bc % C3;
    int y0 = blockIdx.y * 32;
    int tid = threadIdx.x;
    const __nv_bfloat16* in = g_qkv + (size_t)bc * HWP;
    for (int idx = tid; idx < 34*96; idx += 192) {
        int r = idx / 96, cx = (idx % 96) * 2;
        int y = y0 - 1 + r;
        float2 v = (y >= 0 && y < HH)
            ? __bfloat1622float2(*(const __nv_bfloat162*)(in + y*WW + cx))
            : make_float2(0.f, 0.f);
        rows[r][cx] = v.x; rows[r][cx + 1] = v.y;
    }
    __syncthreads();
    float w[9];
    #pragma unroll
    for (int q = 0; q < 9; q++) w[q] = dww[ch*9 + q];
    float bias = dwb[ch];
    __nv_bfloat16* outp = g_qkvd + (size_t)bc * HWP;
    int xc = tid;
    bool hasL = (xc > 0), hasR = (xc < WW - 1);
    float lw[3], mw[3], rw[3];
    #pragma unroll
    for (int r = 0; r < 2; r++) {
        lw[r] = hasL ? rows[r][xc - 1] : 0.f;
        mw[r] = rows[r][xc];
        rw[r] = hasR ? rows[r][xc + 1] : 0.f;
    }
    #pragma unroll
    for (int ry = 0; ry < 32; ry++) {
        int s2 = (ry + 2) % 3;
        lw[s2] = hasL ? rows[ry + 2][xc - 1] : 0.f;
        mw[s2] = rows[ry + 2][xc];
        rw[s2] = hasR ? rows[ry + 2][xc + 1] : 0.f;
        int s0 = ry % 3, s1 = (ry + 1) % 3;
        float acc = bias
            + w[0]*lw[s0] + w[1]*mw[s0] + w[2]*rw[s0]
            + w[3]*lw[s1] + w[4]*mw[s1] + w[5]*rw[s1]
            + w[6]*lw[s2] + w[7]*mw[s2] + w[8]*rw[s2];
        outp[(y0 + ry)*WW + xc] = __float2bfloat16(acc);
    }
}

// ============ K3: Gram + sumsq, bf16 tensor cores ============
__global__ void __launch_bounds__(256) k3_gram()
{
    __shared__ __align__(16) float sm[8*1024];   // 32KB: staging alias + S reduction
    __shared__ float ssq[8][32];
    u32* qs = (u32*)sm;            // 32 x 68 u32 (bf16 px-pairs)
    u32* ks = qs + 32*68;
    int bh = blockIdx.x, chunk = blockIdx.y;
    int b = bh / NH, h = bh % NH;
    int tid = threadIdx.x;
    int w = tid >> 5, lane = tid & 31;
    int g = lane >> 2, tig = lane & 3;
    const __nv_bfloat16* qbase = g_qkvd + ((size_t)b*C3 + h*HD)*HWP + chunk*CHUNK;
    const __nv_bfloat16* kbase = g_qkvd + ((size_t)b*C3 + 96 + h*HD)*HWP + chunk*CHUNK;

    float D[2][4][4];
    #pragma unroll
    for (int m = 0; m < 2; m++)
        #pragma unroll
        for (int n = 0; n < 4; n++)
            #pragma unroll
            for (int c = 0; c < 4; c++) D[m][n][c] = 0.f;
    float acc = 0.f;
    const u32* sq_src = (w < 4) ? qs : ks;
    int wq = (w & 3) * 16;   // u32-word offset of this warp's 32-px quarter

    #pragma unroll 1
    for (int st = 0; st < CHUNK/128; st++) {
        int poff = st * 128;
        // raw copy: 128 px of q,k (bf16 pairs, no conversion)
        #pragma unroll
        for (int it = 0; it < 4; it++) {
            int idx = tid + it*256;                   // 0..1023
            int ci = idx >> 5, wp = (idx & 31) * 2;   // even u32 word
            *(uint2*)(qs + ci*68 + wp) =
                *(const uint2*)((const u32*)(qbase + (size_t)ci*HWP + poff) + wp);
            *(uint2*)(ks + ci*68 + wp) =
                *(const uint2*)((const u32*)(kbase + (size_t)ci*HWP + poff) + wp);
        }
        __syncthreads();

        // warp w owns 16-px K-slice (one k16 step): full 32x32 tile
        {
            u32 A[2][4];
            #pragma unroll
            for (int m = 0; m < 2; m++) {
                A[m][0] = qs[(m*16 + g)*68     + w*8 + tig];
                A[m][1] = qs[(m*16 + g + 8)*68 + w*8 + tig];
                A[m][2] = qs[(m*16 + g)*68     + w*8 + tig + 4];
                A[m][3] = qs[(m*16 + g + 8)*68 + w*8 + tig + 4];
            }
            #pragma unroll
            for (int n = 0; n < 4; n++) {
                u32 b0 = ks[(n*8 + g)*68 + w*8 + tig];
                u32 b1 = ks[(n*8 + g)*68 + w*8 + tig + 4];
                mma16(D[0][n], A[0], b0, b1);
                mma16(D[1][n], A[1], b0, b1);
            }
        }
        // sumsq: warp w covers 32-px quarter of q (w<4) or k (w>=4), ch = lane
        {
            const u32* srow = sq_src + lane*68 + wq;
            #pragma unroll
            for (int t = 0; t < 4; t++) {
                uint4 vv = *(const uint4*)(srow + t*4);
                float2 a0 = unbf(vv.x), a1 = unbf(vv.y);
                float2 a2 = unbf(vv.z), a3 = unbf(vv.w);
                acc += a0.x*a0.x + a0.y*a0.y + a1.x*a1.x + a1.y*a1.y
                     + a2.x*a2.x + a2.y*a2.y + a3.x*a3.x + a3.y*a3.y;
            }
        }
        __syncthreads();
    }

    ssq[w][lane] = acc;
    float* sred = sm;   // staging done; reuse as fp32 reduction buffer
    #pragma unroll
    for (int m = 0; m < 2; m++)
        #pragma unroll
        for (int n = 0; n < 4; n++) {
            int base = w*1024 + (m*16 + g)*32 + n*8 + 2*tig;
            sred[base]       = D[m][n][0];
            sred[base + 1]   = D[m][n][1];
            sred[base + 256] = D[m][n][2];
            sred[base + 257] = D[m][n][3];
        }
    __syncthreads();

    float* Sp = g_Sp + (((size_t)chunk*BB + b)*NH + h)*1024;
    #pragma unroll
    for (int it = 0; it < 4; it++) {
        int e = tid + it*256;
        float s = 0.f;
        #pragma unroll
        for (int w8 = 0; w8 < 8; w8++) s += sred[w8*1024 + e];
        Sp[e] = s;
    }
    float* sqp = g_sqp + ((size_t)chunk*BB + b)*192;
    if (tid < 32)
        sqp[h*HD + tid] = ssq[0][tid] + ssq[1][tid] + ssq[2][tid] + ssq[3][tid];
    else if (tid < 64) {
        int l = tid - 32;
        sqp[96 + h*HD + l] = ssq[4][l] + ssq[5][l] + ssq[6][l] + ssq[7][l];
    }
}

// ============ K4: normalize + relu + softmax -> fp32 A ============
__global__ void __launch_bounds__(256) k4_attn(const float* __restrict__ temp)
{
    int w = threadIdx.x >> 5, lane = threadIdx.x & 31;
    int bh = blockIdx.x*8 + w;
    int b = bh / NH, h = bh % NH;
    float sq = 0.f, sk = 0.f;
    #pragma unroll
    for (int c = 0; c < NCHUNK; c++) {
        const float* sqp = g_sqp + ((size_t)c*BB + b)*192;
        sq += sqp[h*HD + lane];
        sk += sqp[96 + h*HD + lane];
    }
    float nq = fmaxf(sqrtf(sq), 1e-12f);
    float nkv = fmaxf(sqrtf(sk), 1e-12f);
    float tp = temp[h];
    float v[32];
    float mx = 0.f;
    #pragma unroll
    for (int j = 0; j < 32; j++) {
        float nkj = __shfl_sync(0xffffffffu, nkv, j);
        float s = 0.f;
        #pragma unroll
        for (int c = 0; c < NCHUNK; c++)
            s += g_Sp[(((size_t)c*BB + b)*NH + h)*1024 + lane*32 + j];
        s = s / (nq * nkj) * tp;
        s = fmaxf(s, 0.f);
        v[j] = s;
        mx = fmaxf(mx, s);
    }
    float sum = 0.f;
    #pragma unroll
    for (int j = 0; j < 32; j++) { v[j] = expf(v[j] - mx); sum += v[j]; }
    float inv = 1.f / sum;
    #pragma unroll
    for (int j = 0; j < 32; j++)
        g_A[(size_t)bh*1024 + lane*32 + j] = v[j] * inv;
}

// ============ K4b: Wp[b] = projW @ blockdiag(A_b) -> bf16 A-frags ============
__global__ void __launch_bounds__(256) k4b_fuse(const float* __restrict__ projw)
{
    int b = blockIdx.x;
    int tid = threadIdx.x;
    #pragma unroll 1
    for (int t = 0; t < 18; t++) {
        int widx = tid + t*256;          // 0..4607
        int f = widx >> 7, rem = widx & 127;
        int lane = rem >> 2, q = rem & 3;
        int mt = f / 6, s = f % 6;
        int g = lane >> 2, tig = lane & 3;
        int r  = mt*16 + g + (q & 1)*8;
        int kb = s*16 + 2*tig + (q >> 1)*8;
        int h  = kb >> 5, j = kb & 31;
        const float* pw = projw + r*96 + h*32;
        const float* Ab = g_A + ((size_t)b*NH + h)*1024;
        float w0 = 0.f, w1 = 0.f;
        #pragma unroll
        for (int i = 0; i < 32; i++) {
            float p = pw[i];
            w0 += p * Ab[i*32 + j];
            w1 += p * Ab[i*32 + j + 1];
        }
        g_Wp[(size_t)b*4608 + widx] = packbf(w0, w1);
    }
}

// ============ K5: (Wp@v) + residual + shfl-LN2 + FFN ============
__global__ void __launch_bounds__(256) k5_fused(
    const float* __restrict__ x,
    const float* __restrict__ ln2w,  const float* __restrict__ ln2b,
    const float* __restrict__ projb,
    const float* __restrict__ c1b,   const float* __restrict__ c2b,
    const float* __restrict__ betac, const float* __restrict__ gamma,
    float* __restrict__ out)
{
    extern __shared__ __align__(16) u32 smu[];
    u32* bufA = smu;                 // v -> gated g   (48*SP u32)
    u32* bufB = smu + 48*SP;         // yn             (48*SP u32)
    int b  = blockIdx.x / NPXT;
    int p0 = (blockIdx.x % NPXT) * PXT;
    int tid = threadIdx.x;
    int w = tid >> 5, lane = tid & 31;
    int g = lane >> 2, tig = lane & 3;
    int pxw = w * 16;

    // stage 0: v tile -> bufA ch-pair packed
    {
        const __nv_bfloat16* vbase = g_qkvd + ((size_t)b*C3 + 192)*HWP + p0;
        for (int idx = tid; idx < 48*64; idx += 256) {
            int c2 = idx >> 6, j = idx & 63;
            u32 r0 = *((const u32*)(vbase + (size_t)(2*c2)*HWP) + j);
            u32 r1 = *((const u32*)(vbase + (size_t)(2*c2 + 1)*HWP) + j);
            bufA[c2*SP + 2*j]     = __byte_perm(r0, r1, 0x5410);
            bufA[c2*SP + 2*j + 1] = __byte_perm(r0, r1, 0x7632);
        }
    }
    __syncthreads();

    // stage 1: y = x + (Wp@v + pb)*betac -> yreg (registers only)
    float yreg[48];
    const u32* wpk = g_Wp + (size_t)b*4608;
    #pragma unroll 1
    for (int mtp = 0; mtp < 3; mtp++) {
        float D[2][2][4];
        #pragma unroll
        for (int m = 0; m < 2; m++)
            #pragma unroll
            for (int n = 0; n < 2; n++)
                #pragma unroll
                for (int c = 0; c < 4; c++) D[m][n][c] = 0.f;
        #pragma unroll
        for (int s = 0; s < 6; s++) {
            u32 A0[4], A1[4];
            ldAb(A0, wpk, (2*mtp)*6 + s, lane);
            ldAb(A1, wpk, (2*mtp + 1)*6 + s, lane);
            u32 b00 = bufA[(8*s + tig)*SP + pxw + g];
            u32 b01 = bufA[(8*s + tig + 4)*SP + pxw + g];
            u32 b10 = bufA[(8*s + tig)*SP + pxw + 8 + g];
            u32 b11 = bufA[(8*s + tig + 4)*SP + pxw + 8 + g];
            mma16(D[0][0], A0, b00, b01); mma16(D[0][1], A0, b10, b11);
            mma16(D[1][0], A1, b00, b01); mma16(D[1][1], A1, b10, b11);
        }
        #pragma unroll
        for (int m = 0; m < 2; m++) {
            int r0 = (2*mtp + m)*16 + g;
            float pb0 = projb[r0], bc0 = betac[r0];
            float pb1 = projb[r0 + 8], bc1 = betac[r0 + 8];
            #pragma unroll
            for (int n = 0; n < 2; n++) {
                int cl = pxw + n*8 + 2*tig;
                float2 xv0 = *(const float2*)(x + ((size_t)b*CC + r0)*HWP + p0 + cl);
                float2 xv1 = *(const float2*)(x + ((size_t)b*CC + r0 + 8)*HWP + p0 + cl);
                int yi = ((mtp*2 + m)*2 + n)*4;
                yreg[yi]   = xv0.x + (D[m][n][0] + pb0)*bc0;
                yreg[yi+1] = xv0.y + (D[m][n][1] + pb0)*bc0;
                yreg[yi+2] = xv1.x + (D[m][n][2] + pb1)*bc1;
                yreg[yi+3] = xv1.y + (D[m][n][3] + pb1)*bc1;
            }
        }
    }

    // LN2 stats via butterfly shuffles over the 8 g-lanes sharing each pixel
    float ps[4]  = {0.f, 0.f, 0.f, 0.f};
    float ps2[4] = {0.f, 0.f, 0.f, 0.f};
    #pragma unroll
    for (int mtp = 0; mtp < 3; mtp++)
        #pragma unroll
        for (int m = 0; m < 2; m++)
            #pragma unroll
            for (int n = 0; n < 2; n++)
                #pragma unroll
                for (int j = 0; j < 2; j++) {
                    int yi = ((mtp*2 + m)*2 + n)*4;
                    int p = n*2 + j;
                    float v0 = yreg[yi + j], v1 = yreg[yi + 2 + j];
                    ps[p]  += v0 + v1;
                    ps2[p] += v0*v0 + v1*v1;
                }
    #pragma unroll
    for (int mask = 4; mask <= 16; mask <<= 1)
        #pragma unroll
        for (int p = 0; p < 4; p++) {
            ps[p]  += __shfl_xor_sync(0xffffffffu, ps[p],  mask);
            ps2[p] += __shfl_xor_sync(0xffffffffu, ps2[p], mask);
        }
    float mu[4], rs[4];
    #pragma unroll
    for (int p = 0; p < 4; p++) {
        mu[p] = ps[p] * (1.0f/96.0f);
        float var = fmaxf(ps2[p] * (1.0f/96.0f) - mu[p]*mu[p], 0.f);
        rs[p] = rsqrtf(var + 1e-6f);
    }
    // normalize own elements -> bufB (bf16 ch-pairs)
    #pragma unroll
    for (int mtp = 0; mtp < 3; mtp++)
        #pragma unroll
        for (int m = 0; m < 2; m++) {
            int r0 = (2*mtp + m)*16 + g;
            float w0 = ln2w[r0], b0 = ln2b[r0];
            float w1 = ln2w[r0 + 8], b1 = ln2b[r0 + 8];
            #pragma unroll
            for (int n = 0; n < 2; n++)
                #pragma unroll
                for (int j = 0; j < 2; j++) {
                    int yi = ((mtp*2 + m)*2 + n)*4;
                    int p = n*2 + j;
                    int px = pxw + n*8 + 2*tig + j;
                    stbf(bufB, r0,     px, (yreg[yi + j]     - mu[p])*rs[p]*w0 + b0);
                    stbf(bufB, r0 + 8, px, (yreg[yi + 2 + j] - mu[p])*rs[p]*w1 + b1);
                }
        }
    __syncthreads();

    // stage 4: g = (conv1a(yn)+b1)*(conv1b(yn)+b2) -> bufA
    #pragma unroll 1
    for (int mtp = 0; mtp < 3; mtp++) {
        float D1[2][2][4], D2[2][2][4];
        #pragma unroll
        for (int m = 0; m < 2; m++)
            #pragma unroll
            for (int n = 0; n < 2; n++)
                #pragma unroll
                for (int c = 0; c < 4; c++) { D1[m][n][c] = 0.f; D2[m][n][c] = 0.f; }
        #pragma unroll 1
        for (int s = 0; s < 6; s++) {
            u32 A0[4], A1[4], A2[4], A3[4];
            ldAb(A0, g_pk_c1, (2*mtp)*6 + s, lane);
            ldAb(A1, g_pk_c1, (2*mtp + 1)*6 + s, lane);
            ldAb(A2, g_pk_c1, (2*mtp + 6)*6 + s, lane);
            ldAb(A3, g_pk_c1, (2*mtp + 7)*6 + s, lane);
            u32 b00 = bufB[(8*s + tig)*SP + pxw + g];
            u32 b01 = bufB[(8*s + tig + 4)*SP + pxw + g];
            u32 b10 = bufB[(8*s + tig)*SP + pxw + 8 + g];
            u32 b11 = bufB[(8*s + tig + 4)*SP + pxw + 8 + g];
            mma16(D1[0][0], A0, b00, b01); mma16(D1[0][1], A0, b10, b11);
            mma16(D1[1][0], A1, b00, b01); mma16(D1[1][1], A1, b10, b11);
            mma16(D2[0][0], A2, b00, b01); mma16(D2[0][1], A2, b10, b11);
            mma16(D2[1][0], A3, b00, b01); mma16(D2[1][1], A3, b10, b11);
        }
        #pragma unroll
        for (int m = 0; m < 2; m++) {
            int r0 = (2*mtp + m)*16 + g;
            float ba0 = c1b[r0], bb0 = c1b[96 + r0];
            float ba1 = c1b[r0 + 8], bb1 = c1b[96 + r0 + 8];
            #pragma unroll
            for (int n = 0; n < 2; n++) {
                int cl = pxw + n*8 + 2*tig;
                stbf(bufA, r0,     cl,     (D1[m][n][0] + ba0)*(D2[m][n][0] + bb0));
                stbf(bufA, r0,     cl + 1, (D1[m][n][1] + ba0)*(D2[m][n][1] + bb0));
                stbf(bufA, r0 + 8, cl,     (D1[m][n][2] + ba1)*(D2[m][n][2] + bb1));
                stbf(bufA, r0 + 8, cl + 1, (D1[m][n][3] + ba1)*(D2[m][n][3] + bb1));
            }
        }
    }
    __syncthreads();

    // stage 5: out = y + (conv2(g)+cb)*gamma
    #pragma unroll 1
    for (int mtp = 0; mtp < 3; mtp++) {
        float D[2][2][4];
        #pragma unroll
        for (int m = 0; m < 2; m++)
            #pragma unroll
            for (int n = 0; n < 2; n++)
                #pragma unroll
                for (int c = 0; c < 4; c++) D[m][n][c] = 0.f;
        #pragma unroll
        for (int s = 0; s < 6; s++) {
            u32 A0[4], A1[4];
            ldAb(A0, g_pk_c2, (2*mtp)*6 + s, lane);
            ldAb(A1, g_pk_c2, (2*mtp + 1)*6 + s, lane);
            u32 b00 = bufA[(8*s + tig)*SP + pxw + g];
            u32 b01 = bufA[(8*s + tig + 4)*SP + pxw + g];
            u32 b10 = bufA[(8*s + tig)*SP + pxw + 8 + g];
            u32 b11 = bufA[(8*s + tig + 4)*SP + pxw + 8 + g];
            mma16(D[0][0], A0, b00, b01); mma16(D[0][1], A0, b10, b11);
            mma16(D[1][0], A1, b00, b01); mma16(D[1][1], A1, b10, b11);
        }
        #pragma unroll
        for (int m = 0; m < 2; m++) {
            int r0 = (2*mtp + m)*16 + g;
            float cb0 = c2b[r0], gm0 = gamma[r0];
            float cb1 = c2b[r0 + 8], gm1 = gamma[r0 + 8];
            #pragma unroll
            for (int n = 0; n < 2; n++) {
                int cl = pxw + n*8 + 2*tig;
                int yi = ((mtp*2 + m)*2 + n)*4;
                float2 o0, o1;
                o0.x = yreg[yi]   + (D[m][n][0] + cb0)*gm0;
                o0.y = yreg[yi+1] + (D[m][n][1] + cb0)*gm0;
                o1.x = yreg[yi+2] + (D[m][n][2] + cb1)*gm1;
                o1.y = yreg[yi+3] + (D[m][n][3] + cb1)*gm1;
                *(float2*)(out + ((size_t)b*CC + r0)*HWP + p0 + cl) = o0;
                *(float2*)(out + ((size_t)b*CC + r0 + 8)*HWP + p0 + cl) = o1;
            }
        }
    }
}

extern "C" void kernel_launch(void* const* d_in, const int* in_sizes, int n_in,
                              void* d_out, int out_size) {
    (void)in_sizes; (void)n_in; (void)out_size;
    const float* x      = (const float*)d_in[0];
    const float* ln1_w  = (const float*)d_in[1];
    const float* ln1_b  = (const float*)d_in[2];
    const float* ln2_w  = (const float*)d_in[3];
    const float* ln2_b  = (const float*)d_in[4];
    const float* qkv_w  = (const float*)d_in[5];
    const float* qkv_b  = (const float*)d_in[6];
    const float* dw_w   = (const float*)d_in[7];
    const float* dw_b   = (const float*)d_in[8];
    const float* temp   = (const float*)d_in[9];
    const float* proj_w = (const float*)d_in[10];
    const float* proj_b = (const float*)d_in[11];
    const float* c1_w   = (const float*)d_in[12];
    const float* c1_b   = (const float*)d_in[13];
    const float* c2_w   = (const float*)d_in[14];
    const float* c2_b   = (const float*)d_in[15];
    const float* betac  = (const float*)d_in[16];
    const float* gamma  = (const float*)d_in[17];
    float* out = (float*)d_out;

    int smem1 = 48*SP*4;     // 26112 B
    int smem5 = 96*SP*4;     // 52224 B
    cudaFuncSetAttribute(k1_ln_qkv, cudaFuncAttributeMaxDynamicSharedMemorySize, smem1);
    cudaFuncSetAttribute(k5_fused,  cudaFuncAttributeMaxDynamicSharedMemorySize, smem5);

    k0_pack<<<126, 256>>>(qkv_w, proj_w, c1_w, c2_w);
    k1_ln_qkv<<<BB*NPXT, 256, smem1>>>(x, ln1_w, ln1_b, qkv_b);
    k2_dw<<<dim3(BB*C3, HH/32), 192>>>(dw_w, dw_b);
    k3_gram<<<dim3(BB*NH, NCHUNK), 256>>>();
    k4_attn<<<3, 256>>>(temp);
    k4b_fuse<<<BB, 256>>>(proj_w);
    k5_fused<<<BB*NPXT, 256, smem5>>>(x, ln2_w, ln2_b, proj_b,
                                      c1_b, c2_b, betac, gamma, out);
}